// round 7
// baseline (speedup 1.0000x reference)
#include <cuda_runtime.h>
#include <math.h>

#define BB 2
#define NTOK 8192
#define DIMX 512
#define NH 8
#define DH 64
#define ML 256
#define BHN 16

__device__ float g_xn[BB*NTOK*DIMX];
__device__ float g_q [BHN*NTOK*DH];
__device__ float g_k [BHN*NTOK*DH];
__device__ float g_v [BHN*NTOK*DH];
__device__ float g_ql[BHN*ML*DH];
__device__ float g_kl[BHN*ML*DH];
__device__ float g_a2[BHN*ML*ML];
__device__ float g_z0[BHN*ML*ML];
__device__ float g_z1[BHN*ML*ML];
__device__ float g_xz[BHN*ML*ML];
__device__ float g_t1[BHN*ML*ML];
__device__ float g_t2[BHN*ML*ML];
__device__ float g_sim3[(size_t)BHN*ML*NTOK];
__device__ float g_a3vp[8*BHN*ML*DH];
__device__ float g_a3v [BHN*ML*DH];
__device__ float g_Z2  [BHN*ML*DH];
__device__ float g_attn[BB*NTOK*DIMX];
__device__ float g_scal[2];

// ================= tf32 tensor-core helpers =================
__device__ __forceinline__ float thi(float x){
    return __uint_as_float(__float_as_uint(x)&0xffffe000u);
}
__device__ __forceinline__ void mma8(float* c, const unsigned* a, const unsigned* b){
    asm volatile("mma.sync.aligned.m16n8k8.row.col.f32.tf32.tf32.f32 "
        "{%0,%1,%2,%3},{%4,%5,%6,%7},{%8,%9},{%0,%1,%2,%3};"
        : "+f"(c[0]),"+f"(c[1]),"+f"(c[2]),"+f"(c[3])
        : "r"(a[0]),"r"(a[1]),"r"(a[2]),"r"(a[3]),"r"(b[0]),"r"(b[1]));
}

// Core tf32-split block GEMM: 128x128 tile, K multiple of 16.
#define TC_GEMM_LOOP(Aptr, LDA, Bptr, LDB, KTOT)                                        \
    for(int k0=0;k0<(KTOT);k0+=16){                                                     \
        {   int r=t>>1, h=(t&1)*8;                                                      \
            const float* ap=(Aptr)+(size_t)(bm+r)*(LDA)+k0+h;                           \
            float4 v0=*(const float4*)ap; float4 v1=*(const float4*)(ap+4);             \
            float xs[8]={v0.x,v0.y,v0.z,v0.w,v1.x,v1.y,v1.z,v1.w};                      \
            _Pragma("unroll")                                                           \
            for(int i=0;i<8;i++){ float hv=thi(xs[i]);                                  \
                Ahi[r][h+i]=hv; Alo[r][h+i]=thi(xs[i]-hv); } }                          \
        {   int kk=t>>4, n=(t&15)*8;                                                    \
            const float* bp=(Bptr)+(size_t)(k0+kk)*(LDB)+bn+n;                          \
            float4 v0=*(const float4*)bp; float4 v1=*(const float4*)(bp+4);             \
            float xs[8]={v0.x,v0.y,v0.z,v0.w,v1.x,v1.y,v1.z,v1.w};                      \
            _Pragma("unroll")                                                           \
            for(int i=0;i<8;i++){ float hv=thi(xs[i]);                                  \
                Bhi[kk][n+i]=hv; Blo[kk][n+i]=thi(xs[i]-hv); } }                        \
        __syncthreads();                                                                \
        _Pragma("unroll")                                                               \
        for(int kk=0;kk<16;kk+=8){                                                      \
            unsigned ah[4][4], al[4][4], bh[4][2], bl[4][2];                            \
            _Pragma("unroll")                                                           \
            for(int mt=0;mt<4;mt++){                                                    \
                int mr=wm*64+mt*16+(lane>>2); int kc=kk+(lane&3);                       \
                ah[mt][0]=__float_as_uint(Ahi[mr][kc]);                                 \
                ah[mt][1]=__float_as_uint(Ahi[mr+8][kc]);                               \
                ah[mt][2]=__float_as_uint(Ahi[mr][kc+4]);                               \
                ah[mt][3]=__float_as_uint(Ahi[mr+8][kc+4]);                             \
                al[mt][0]=__float_as_uint(Alo[mr][kc]);                                 \
                al[mt][1]=__float_as_uint(Alo[mr+8][kc]);                               \
                al[mt][2]=__float_as_uint(Alo[mr][kc+4]);                               \
                al[mt][3]=__float_as_uint(Alo[mr+8][kc+4]);                             \
            }                                                                           \
            _Pragma("unroll")                                                           \
            for(int nt=0;nt<4;nt++){                                                    \
                int col=wn*32+nt*8+(lane>>2); int kc=kk+(lane&3);                       \
                bh[nt][0]=__float_as_uint(Bhi[kc][col]);                                \
                bh[nt][1]=__float_as_uint(Bhi[kc+4][col]);                              \
                bl[nt][0]=__float_as_uint(Blo[kc][col]);                                \
                bl[nt][1]=__float_as_uint(Blo[kc+4][col]);                              \
            }                                                                           \
            _Pragma("unroll")                                                           \
            for(int mt=0;mt<4;mt++)                                                     \
                _Pragma("unroll")                                                       \
                for(int nt=0;nt<4;nt++){                                                \
                    mma8(acc[mt][nt], ah[mt], bh[nt]);                                  \
                    mma8(acc[mt][nt], ah[mt], bl[nt]);                                  \
                    mma8(acc[mt][nt], al[mt], bh[nt]);                                  \
                }                                                                       \
        }                                                                               \
        __syncthreads();                                                                \
    }

// ---- tf32 QKV GEMM ----
__global__ void tcqkv_kernel(const float* __restrict__ W){
    __shared__ float Ahi[128][20], Alo[128][20], Bhi[16][136], Blo[16][136];
    int t=threadIdx.x, lane=t&31, wid=t>>5;
    int wm=wid&1, wn=wid>>1;
    int bn=blockIdx.x*128, bm=blockIdx.y*128;
    float acc[4][4][4];
    #pragma unroll
    for(int a=0;a<4;a++)
        #pragma unroll
        for(int b=0;b<4;b++)
            #pragma unroll
            for(int c=0;c<4;c++) acc[a][b][c]=0.f;
    TC_GEMM_LOOP(g_xn, DIMX, W, 1536, 512)
    #pragma unroll
    for(int mt=0;mt<4;mt++)
        #pragma unroll
        for(int nt=0;nt<4;nt++)
            #pragma unroll
            for(int ci=0;ci<4;ci++){
                int row=bm+wm*64+mt*16+(lane>>2)+((ci>>1)<<3);
                int col=bn+wn*32+nt*8+((lane&3)<<1)+(ci&1);
                int b_=row>>13, n=row&8191;
                int s=col>>9, inner=col&511, h=inner>>6, d=inner&63;
                size_t o=((size_t)((b_*NH+h)*NTOK+n))*DH+d;
                float val=acc[mt][nt][ci];
                if(s==0) g_q[o]=val*0.125f;
                else if(s==1) g_k[o]=val;
                else g_v[o]=val;
            }
}

// ---- tf32 out GEMM: out = x + attn @ W + bias ----
__global__ void tcout_kernel(const float* __restrict__ W, const float* __restrict__ bias,
                             const float* __restrict__ x, float* __restrict__ out){
    __shared__ float Ahi[128][20], Alo[128][20], Bhi[16][136], Blo[16][136];
    int t=threadIdx.x, lane=t&31, wid=t>>5;
    int wm=wid&1, wn=wid>>1;
    int bn=blockIdx.x*128, bm=blockIdx.y*128;
    float acc[4][4][4];
    #pragma unroll
    for(int a=0;a<4;a++)
        #pragma unroll
        for(int b=0;b<4;b++)
            #pragma unroll
            for(int c=0;c<4;c++) acc[a][b][c]=0.f;
    TC_GEMM_LOOP(g_attn, DIMX, W, DIMX, 512)
    #pragma unroll
    for(int mt=0;mt<4;mt++)
        #pragma unroll
        for(int nt=0;nt<4;nt++)
            #pragma unroll
            for(int ci=0;ci<4;ci++){
                int row=bm+wm*64+mt*16+(lane>>2)+((ci>>1)<<3);
                int col=bn+wn*32+nt*8+((lane&3)<<1)+(ci&1);
                size_t o=(size_t)row*DIMX+col;
                out[o]=x[o]+bias[col]+acc[mt][nt][ci];
            }
}

// ================= fp32 SIMT GEMM cores (rest of pipeline) =================
__device__ __forceinline__ void loadA_kmajor(float (*As)[129], const float* __restrict__ Ag,
                                             int lda, int bm, int k0, int t){
    #pragma unroll
    for(int i=0;i<4;i++){
        int q=t+(i<<8); int r=q>>3; int kq=q&7;
        float4 v=*(const float4*)(Ag+(size_t)(bm+r)*lda+k0+(kq<<2));
        As[(kq<<2)+0][r]=v.x; As[(kq<<2)+1][r]=v.y;
        As[(kq<<2)+2][r]=v.z; As[(kq<<2)+3][r]=v.w;
    }
}
__device__ __forceinline__ void loadB_kn64(float (*Bs)[65], const float* __restrict__ Bg,
                                           int ldb, int bn, int k0, int t){
    #pragma unroll
    for(int i=0;i<2;i++){
        int q=t+(i<<8); int kk=q>>4; int cq=q&15;
        float4 v=*(const float4*)(Bg+(size_t)(k0+kk)*ldb+bn+(cq<<2));
        Bs[kk][(cq<<2)+0]=v.x; Bs[kk][(cq<<2)+1]=v.y;
        Bs[kk][(cq<<2)+2]=v.z; Bs[kk][(cq<<2)+3]=v.w;
    }
}
__device__ __forceinline__ void fma128(const float (*As)[129], const float (*Bs)[129],
                                       float acc[8][8], int tx, int ty){
    #pragma unroll
    for(int kk=0;kk<32;kk++){
        float a[8], b[8];
        #pragma unroll
        for(int i=0;i<8;i++) a[i]=As[kk][ty*8+i];
        #pragma unroll
        for(int j=0;j<8;j++) b[j]=Bs[kk][tx+(j<<4)];
        #pragma unroll
        for(int i=0;i<8;i++)
            #pragma unroll
            for(int j=0;j<8;j++) acc[i][j]+=a[i]*b[j];
    }
}
__device__ __forceinline__ void fma64(const float (*As)[129], const float (*Bs)[65],
                                      float acc[8][4], int tx, int ty){
    #pragma unroll
    for(int kk=0;kk<32;kk++){
        float a[8], b[4];
        #pragma unroll
        for(int i=0;i<8;i++) a[i]=As[kk][ty*8+i];
        #pragma unroll
        for(int j=0;j<4;j++) b[j]=Bs[kk][tx+(j<<4)];
        #pragma unroll
        for(int i=0;i<8;i++)
            #pragma unroll
            for(int j=0;j<4;j++) acc[i][j]+=a[i]*b[j];
    }
}
__device__ __forceinline__ void tile_fma32(const float (*As)[65], const float (*Bs)[65],
                                           float acc[4][4], int tx, int ty){
    #pragma unroll
    for(int kk=0;kk<32;kk++){
        float a[4], b[4];
        #pragma unroll
        for(int i=0;i<4;i++) a[i]=As[kk][ty*4+i];
        #pragma unroll
        for(int j=0;j<4;j++) b[j]=Bs[kk][tx+16*j];
        #pragma unroll
        for(int i=0;i<4;i++)
            #pragma unroll
            for(int j=0;j<4;j++) acc[i][j]+=a[i]*b[j];
    }
}

// ---- LayerNorm ----
__global__ void ln_kernel(const float* __restrict__ x, const float* __restrict__ w,
                          const float* __restrict__ bp){
    int row=blockIdx.x, t=threadIdx.x;
    const float* xr = x + (size_t)row*DIMX;
    float v0=xr[t], v1=xr[t+256];
    float s=v0+v1, sq=v0*v0+v1*v1;
    __shared__ float r1[8], r2[8];
    #pragma unroll
    for(int o=16;o;o>>=1){ s+=__shfl_xor_sync(~0u,s,o); sq+=__shfl_xor_sync(~0u,sq,o); }
    if((t&31)==0){ r1[t>>5]=s; r2[t>>5]=sq; }
    __syncthreads();
    float ss=0, qq=0;
    #pragma unroll
    for(int i=0;i<8;i++){ ss+=r1[i]; qq+=r2[i]; }
    float mean=ss*(1.f/512.f);
    float rstd=rsqrtf(qq*(1.f/512.f)-mean*mean+1e-5f);
    g_xn[(size_t)row*DIMX+t]     = (v0-mean)*rstd*w[t]+bp[t];
    g_xn[(size_t)row*DIMX+t+256] = (v1-mean)*rstd*w[t+256]+bp[t+256];
}

// ---- Landmarks ----
__global__ void landmark_kernel(){
    int blk=blockIdx.x, bh=blk>>8, m=blk&255, d=threadIdx.x;
    const float* qp=g_q+((size_t)(bh*NTOK+m*32))*DH+d;
    const float* kp=g_k+((size_t)(bh*NTOK+m*32))*DH+d;
    float sq=0,sk=0;
    #pragma unroll
    for(int j=0;j<32;j++){ sq+=qp[(size_t)j*DH]; sk+=kp[(size_t)j*DH]; }
    g_ql[(bh*ML+m)*DH+d]=sq*(1.f/32.f);
    g_kl[(bh*ML+m)*DH+d]=sk*(1.f/32.f);
}

// ---- generic sim: C[M x N] = A[M x 64] @ B[N x 64]^T ----
__global__ void sim_kernel(const float* __restrict__ Abase, const float* __restrict__ Bbase,
                           float* __restrict__ Cbase, size_t aBH, size_t bBH, size_t cBH, int ldC){
    __shared__ float As[32][129], Bs[32][129];
    int t=threadIdx.x, tx=t&15, ty=t>>4;
    int bh=blockIdx.z;
    int bn=blockIdx.x*128, bm=blockIdx.y*128;
    const float* A=Abase+(size_t)bh*aBH;
    const float* B=Bbase+(size_t)bh*bBH;
    float* C=Cbase+(size_t)bh*cBH;
    float acc[8][8]={};
    for(int k0=0;k0<64;k0+=32){
        loadA_kmajor(As, A, DH, bm, k0, t);
        loadA_kmajor(Bs, B, DH, bn, k0, t);
        __syncthreads();
        fma128(As,Bs,acc,tx,ty);
        __syncthreads();
    }
    #pragma unroll
    for(int i=0;i<8;i++)
        #pragma unroll
        for(int j=0;j<8;j++)
            C[(size_t)(bm+ty*8+i)*ldC + bn+tx+(j<<4)]=acc[i][j];
}

// ---- softmax over rows of 256, in place ----
__global__ void softmax256_kernel(float* __restrict__ base){
    int w=threadIdx.x>>5, lane=threadIdx.x&31;
    size_t row=(size_t)blockIdx.x*8+w;
    float* p=base+row*ML;
    float4 v0=*(float4*)(p+lane*8);
    float4 v1=*(float4*)(p+lane*8+4);
    float mx=fmaxf(fmaxf(fmaxf(v0.x,v0.y),fmaxf(v0.z,v0.w)),
                   fmaxf(fmaxf(v1.x,v1.y),fmaxf(v1.z,v1.w)));
    #pragma unroll
    for(int o=16;o;o>>=1) mx=fmaxf(mx,__shfl_xor_sync(~0u,mx,o));
    v0.x=__expf(v0.x-mx); v0.y=__expf(v0.y-mx); v0.z=__expf(v0.z-mx); v0.w=__expf(v0.w-mx);
    v1.x=__expf(v1.x-mx); v1.y=__expf(v1.y-mx); v1.z=__expf(v1.z-mx); v1.w=__expf(v1.w-mx);
    float s=v0.x+v0.y+v0.z+v0.w+v1.x+v1.y+v1.z+v1.w;
    #pragma unroll
    for(int o=16;o;o>>=1) s+=__shfl_xor_sync(~0u,s,o);
    float inv=1.f/s;
    v0.x*=inv; v0.y*=inv; v0.z*=inv; v0.w*=inv;
    v1.x*=inv; v1.y*=inv; v1.z*=inv; v1.w*=inv;
    *(float4*)(p+lane*8)=v0;
    *(float4*)(p+lane*8+4)=v1;
}

// ---- pinv init ----
__global__ void scal_reset_kernel(){ g_scal[0]=0.f; g_scal[1]=0.f; }

__global__ void pinv_sums_kernel(){
    int bh=blockIdx.x, t=threadIdx.x;
    const float* A=g_a2+((size_t)bh<<16);
    float rs=0, cs=0;
    const float4* Ar=(const float4*)(A+(size_t)t*ML);
    #pragma unroll
    for(int j=0;j<64;j++){ float4 v=Ar[j]; rs+=fabsf(v.x)+fabsf(v.y)+fabsf(v.z)+fabsf(v.w); }
    for(int j=0;j<ML;j++) cs+=fabsf(A[(size_t)j*ML+t]);
    #pragma unroll
    for(int o=16;o;o>>=1){ rs=fmaxf(rs,__shfl_xor_sync(~0u,rs,o)); cs=fmaxf(cs,__shfl_xor_sync(~0u,cs,o)); }
    __shared__ float r1[8], r2[8];
    if((t&31)==0){ r1[t>>5]=rs; r2[t>>5]=cs; }
    __syncthreads();
    if(t==0){
        float m1=r1[0], m2=r2[0];
        #pragma unroll
        for(int k=1;k<8;k++){ m1=fmaxf(m1,r1[k]); m2=fmaxf(m2,r2[k]); }
        atomicMax((int*)&g_scal[0], __float_as_int(m1));
        atomicMax((int*)&g_scal[1], __float_as_int(m2));
    }
}

__global__ void zinit_kernel(){
    int e=blockIdx.x*256+threadIdx.x;
    float inv=1.f/(g_scal[0]*g_scal[1]);
    int bh=e>>16, r=(e>>8)&255, c=e&255;
    g_z0[e]=g_a2[(bh<<16)+(c<<8)+r]*inv;
}

// ---- batched 256^3: C = alpha * A @ (cdiag*I - B) ----
__global__ void mm256_kernel(const float* __restrict__ Ag, const float* __restrict__ Bg,
                             float* __restrict__ Cg, float cdiag, float alpha){
    int bh=blockIdx.x;
    const float* A=Ag+((size_t)bh<<16);
    const float* B=Bg+((size_t)bh<<16);
    float* C=Cg+((size_t)bh<<16);
    int bm=blockIdx.y*64, bn=blockIdx.z*64;
    __shared__ float As[32][65], Bs[32][65];
    int t=threadIdx.x, tx=t&15, ty=t>>4;
    float acc[4][4]={};
    for(int k0=0;k0<256;k0+=32){
        #pragma unroll
        for(int i=0;i<8;i++){ int idx=t+(i<<8); int r=idx>>5,kk=idx&31;
            As[kk][r]=A[(size_t)(bm+r)*256+k0+kk]; }
        #pragma unroll
        for(int i=0;i<8;i++){ int idx=t+(i<<8); int kk=idx>>6,c=idx&63;
            int gk=k0+kk, gc=bn+c;
            float bv=B[(size_t)gk*256+gc];
            Bs[kk][c]=(gk==gc)?(cdiag-bv):(-bv); }
        __syncthreads();
        tile_fma32(As,Bs,acc,tx,ty);
        __syncthreads();
    }
    #pragma unroll
    for(int i=0;i<4;i++)
        #pragma unroll
        for(int j=0;j<4;j++)
            C[(size_t)(bm+ty*4+i)*256+bn+tx+(j<<4)]=alpha*acc[i][j];
}

// ---- softmax rows of 8192 ----
__global__ void softmax3_kernel(){
    int row=blockIdx.x, t=threadIdx.x;
    float* p=g_sim3+(size_t)row*NTOK;
    float v[32], mx=-3.0e38f;
    #pragma unroll
    for(int i=0;i<32;i++){ v[i]=p[t+(i<<8)]; mx=fmaxf(mx,v[i]); }
    __shared__ float red[8];
    #pragma unroll
    for(int o=16;o;o>>=1) mx=fmaxf(mx,__shfl_xor_sync(~0u,mx,o));
    if((t&31)==0) red[t>>5]=mx;
    __syncthreads();
    mx=red[0];
    #pragma unroll
    for(int k=1;k<8;k++) mx=fmaxf(mx,red[k]);
    float s=0;
    #pragma unroll
    for(int i=0;i<32;i++){ v[i]=__expf(v[i]-mx); s+=v[i]; }
    #pragma unroll
    for(int o=16;o;o>>=1) s+=__shfl_xor_sync(~0u,s,o);
    __syncthreads();
    if((t&31)==0) red[t>>5]=s;
    __syncthreads();
    s=0;
    #pragma unroll
    for(int k=0;k<8;k++) s+=red[k];
    float inv=1.f/s;
    #pragma unroll
    for(int i=0;i<32;i++) p[t+(i<<8)]=v[i]*inv;
}

// ---- a3 @ v split-K ----
__global__ void a3v_kernel(){
    __shared__ float As[32][129], Bs[32][65];
    int ksp=blockIdx.x, bm=blockIdx.y*128, bh=blockIdx.z;
    int t=threadIdx.x, tx=t&15, ty=t>>4;
    float acc[8][4]={};
    const float* Ap=g_sim3+(size_t)(bh*ML)*NTOK;
    const float* Vp=g_v+(size_t)bh*NTOK*DH;
    int kbeg=ksp*1024;
    for(int k0=kbeg;k0<kbeg+1024;k0+=32){
        loadA_kmajor(As, Ap, NTOK, bm, k0, t);
        loadB_kn64(Bs, Vp, DH, 0, k0, t);
        __syncthreads();
        fma64(As,Bs,acc,tx,ty);
        __syncthreads();
    }
    #pragma unroll
    for(int i=0;i<8;i++)
        #pragma unroll
        for(int j=0;j<4;j++)
            g_a3vp[(size_t)(ksp*BHN+bh)*ML*DH+(bm+ty*8+i)*DH+tx+(j<<4)]=acc[i][j];
}

__global__ void a3v_reduce_kernel(){
    int e=blockIdx.x*256+threadIdx.x;
    float s=0;
    #pragma unroll
    for(int k=0;k<8;k++) s+=g_a3vp[(size_t)k*BHN*ML*DH+e];
    g_a3v[e]=s;
}

// ---- Z2 = z_final @ a3v ----
__global__ void z2_kernel(){
    __shared__ float As[32][129], Bs[32][65];
    int bm=blockIdx.x*128, bh=blockIdx.y;
    const float* A=g_z0+((size_t)bh<<16);
    const float* Bp=g_a3v+(size_t)bh*ML*DH;
    int t=threadIdx.x, tx=t&15, ty=t>>4;
    float acc[8][4]={};
    for(int k0=0;k0<256;k0+=32){
        loadA_kmajor(As, A, ML, bm, k0, t);
        loadB_kn64(Bs, Bp, DH, 0, k0, t);
        __syncthreads();
        fma64(As,Bs,acc,tx,ty);
        __syncthreads();
    }
    #pragma unroll
    for(int i=0;i<8;i++)
        #pragma unroll
        for(int j=0;j<4;j++)
            g_Z2[(size_t)bh*ML*DH+(bm+ty*8+i)*DH+tx+(j<<4)]=acc[i][j];
}

// ---- depthwise conv residual ----
__global__ void conv_kernel(const float* __restrict__ cw){
    int idx=blockIdx.x*256+threadIdx.x;
    int d=idx&63, n=(idx>>6)&8191, bh=idx>>19;
    int h=bh&7;
    const float* vp=g_v+(size_t)bh*NTOK*DH+d;
    float s=0;
    #pragma unroll
    for(int kk=0;kk<33;kk++){
        int j=n+kk-16;
        if(j>=0 && j<NTOK) s+=cw[h*33+kk]*vp[(size_t)j*DH];
    }
    g_attn[((size_t)((bh>>3)*NTOK+n))*DIMX+h*64+d]=s;
}

// ---- g_attn += a1 @ Z2 ----
__global__ void a1z2_kernel(){
    __shared__ float As[32][129], Bs[32][65];
    int bm=blockIdx.x*128, bh=blockIdx.y;
    const float* A=g_sim3+(size_t)bh*NTOK*ML;
    const float* Bp=g_Z2+(size_t)bh*ML*DH;
    int t=threadIdx.x, tx=t&15, ty=t>>4;
    float acc[8][4]={};
    for(int k0=0;k0<256;k0+=32){
        loadA_kmajor(As, A, ML, bm, k0, t);
        loadB_kn64(Bs, Bp, DH, 0, k0, t);
        __syncthreads();
        fma64(As,Bs,acc,tx,ty);
        __syncthreads();
    }
    int b=bh>>3, h=bh&7;
    #pragma unroll
    for(int i=0;i<8;i++){
        size_t base=((size_t)(b*NTOK+bm+ty*8+i))*DIMX+h*64;
        #pragma unroll
        for(int j=0;j<4;j++)
            g_attn[base+tx+(j<<4)]+=acc[i][j];
    }
}

extern "C" void kernel_launch(void* const* d_in, const int* in_sizes, int n_in,
                              void* d_out, int out_size){
    const float* x    = (const float*)d_in[0];
    const float* ln_w = (const float*)d_in[2];
    const float* ln_b = (const float*)d_in[3];
    const float* wqkv = (const float*)d_in[4];
    const float* wout = (const float*)d_in[5];
    const float* bout = (const float*)d_in[6];
    const float* cw   = (const float*)d_in[7];
    float* out = (float*)d_out;

    float *z0,*z1,*a2p,*xz,*t1,*t2,*qlp,*klp,*qp,*kp,*sim3p;
    cudaGetSymbolAddress((void**)&z0, g_z0);
    cudaGetSymbolAddress((void**)&z1, g_z1);
    cudaGetSymbolAddress((void**)&a2p, g_a2);
    cudaGetSymbolAddress((void**)&xz, g_xz);
    cudaGetSymbolAddress((void**)&t1, g_t1);
    cudaGetSymbolAddress((void**)&t2, g_t2);
    cudaGetSymbolAddress((void**)&qlp, g_ql);
    cudaGetSymbolAddress((void**)&klp, g_kl);
    cudaGetSymbolAddress((void**)&qp, g_q);
    cudaGetSymbolAddress((void**)&kp, g_k);
    cudaGetSymbolAddress((void**)&sim3p, g_sim3);

    ln_kernel<<<BB*NTOK, 256>>>(x, ln_w, ln_b);
    tcqkv_kernel<<<dim3(12,128), 256>>>(wqkv);
    landmark_kernel<<<BHN*ML, 64>>>();

    // a2 = softmax(ql @ kl^T) via GEMM + row softmax
    sim_kernel<<<dim3(2,2,BHN), 256>>>(qlp, klp, a2p,
        (size_t)ML*DH, (size_t)ML*DH, (size_t)ML*ML, ML);
    softmax256_kernel<<<BHN*ML/8, 256>>>(a2p);

    scal_reset_kernel<<<1,1>>>();
    pinv_sums_kernel<<<BHN, 256>>>();
    zinit_kernel<<<4096, 256>>>();

    float* zc=z0; float* za=z1;
    for(int it=0; it<6; it++){
        mm256_kernel<<<dim3(BHN,4,4),256>>>(a2p, zc, xz, 0.f, -1.f);
        mm256_kernel<<<dim3(BHN,4,4),256>>>(xz, xz, t1, 7.f, 1.f);
        mm256_kernel<<<dim3(BHN,4,4),256>>>(xz, t1, t2, 15.f, 1.f);
        mm256_kernel<<<dim3(BHN,4,4),256>>>(zc, t2, za, 13.f, 0.25f);
        float* tmp=zc; zc=za; za=tmp;
    }

    // sim3 = ql @ k^T
    sim_kernel<<<dim3(64,2,BHN), 256>>>(qlp, kp, sim3p,
        (size_t)ML*DH, (size_t)NTOK*DH, (size_t)ML*NTOK, NTOK);
    softmax3_kernel<<<BHN*ML, 256>>>();
    a3v_kernel<<<dim3(8,2,BHN), 256>>>();
    a3v_reduce_kernel<<<1024, 256>>>();
    z2_kernel<<<dim3(2,BHN), 256>>>();
    conv_kernel<<<32768, 256>>>(cw);

    // sim1 = q @ kl^T
    sim_kernel<<<dim3(2,64,BHN), 256>>>(qp, klp, sim3p,
        (size_t)NTOK*DH, (size_t)ML*DH, (size_t)NTOK*ML, ML);
    softmax256_kernel<<<BHN*NTOK/8, 256>>>(sim3p);
    a1z2_kernel<<<dim3(64,BHN), 256>>>();
    tcout_kernel<<<dim3(4,128), 256>>>(wout, bout, x, out);
}

// round 10
// speedup vs baseline: 1.1001x; 1.1001x over previous
#include <cuda_runtime.h>
#include <cuda_bf16.h>
#include <math.h>
#include <stdint.h>

#define BB 2
#define NTOK 8192
#define DIMX 512
#define NH 8
#define DH 64
#define ML 256
#define BHN 16

__device__ float g_q [BHN*NTOK*DH];
__device__ float g_k [BHN*NTOK*DH];
__device__ float g_v [BHN*NTOK*DH];
__device__ float g_ql[BHN*ML*DH];
__device__ float g_kl[BHN*ML*DH];
__device__ float g_a2[BHN*ML*ML];
__device__ float g_z0[BHN*ML*ML];
__device__ float g_z1[BHN*ML*ML];
__device__ float g_xz[BHN*ML*ML];
__device__ float g_t1[BHN*ML*ML];
__device__ float g_t2[BHN*ML*ML];
__device__ float g_sim3[(size_t)BHN*ML*NTOK];
__device__ float g_a3vp[8*BHN*ML*DH];
__device__ float g_a3v [BHN*ML*DH];
__device__ float g_Z2  [BHN*ML*DH];
__device__ float g_attn[BB*NTOK*DIMX];
__device__ float g_scal[2];
// bf16 hi/lo operand buffers
__device__ __nv_bfloat16 g_bhi[BB*NTOK*DIMX];
__device__ __nv_bfloat16 g_blo[BB*NTOK*DIMX];
__device__ __nv_bfloat16 g_wqhi[1536*512];
__device__ __nv_bfloat16 g_wqlo[1536*512];
__device__ __nv_bfloat16 g_wohi[512*512];
__device__ __nv_bfloat16 g_wolo[512*512];

// ================= bf16 mma.sync (base ISA, works on plain sm_103) =================
__device__ __forceinline__ void mma16816(float* c, const uint32_t* a, const uint32_t* b){
    asm volatile("mma.sync.aligned.m16n8k16.row.col.f32.bf16.bf16.f32 "
        "{%0,%1,%2,%3},{%4,%5,%6,%7},{%8,%9},{%0,%1,%2,%3};"
        : "+f"(c[0]),"+f"(c[1]),"+f"(c[2]),"+f"(c[3])
        : "r"(a[0]),"r"(a[1]),"r"(a[2]),"r"(a[3]),"r"(b[0]),"r"(b[1]));
}

// bf16-split GEMM: C[128x128] = A @ B^T over Keff = 3*512
// seg0 Ahi*Bhi, seg1 Ahi*Blo, seg2 Alo*Bhi. A row-major [M][512] bf16,
// B transposed [N][512] bf16. Pair-packed smem: P[kp][col], pad 136 ->
// bank = (8*kp + col) & 31, conflict-free for the quad fragment pattern.
// mode 0: qkv scatter epilogue; mode 1: out = x + bias + C.
__global__ void __launch_bounds__(256) bf_gemm(
    const __nv_bfloat16* __restrict__ Ahi, const __nv_bfloat16* __restrict__ Alo,
    const __nv_bfloat16* __restrict__ BhiT, const __nv_bfloat16* __restrict__ BloT,
    int mode, const float* __restrict__ xres, const float* __restrict__ bias,
    float* __restrict__ outp)
{
    __shared__ uint32_t Ap[32][136];
    __shared__ uint32_t Bp[32][136];
    int t=threadIdx.x, lane=t&31, wid=t>>5;
    int g=lane>>2, tig=lane&3;
    int wm=wid&1, wn=wid>>1;
    int bn=blockIdx.x*128, bm=blockIdx.y*128;
    float acc[4][4][4];
    #pragma unroll
    for(int a=0;a<4;a++)
        #pragma unroll
        for(int b=0;b<4;b++)
            #pragma unroll
            for(int c=0;c<4;c++) acc[a][b][c]=0.f;

    for(int blk=0;blk<24;blk++){
        int seg=blk>>3, kb=(blk&7)<<6;   // 64 bf16 k per stage
        const __nv_bfloat16* Asrc=(seg<2)?Ahi:Alo;
        const __nv_bfloat16* Bsrc=(seg==1)?BloT:BhiT;
        // load A tile: 128 rows x 32 kp (u32 pairs). j -> kq(0..7), row(0..127)
        #pragma unroll
        for(int i=0;i<4;i++){
            int j=t+(i<<8); int kq=j>>7, row=j&127;
            uint4 v=*(const uint4*)(Asrc+(size_t)(bm+row)*512+kb+(kq<<3));
            Ap[(kq<<2)+0][row]=v.x; Ap[(kq<<2)+1][row]=v.y;
            Ap[(kq<<2)+2][row]=v.z; Ap[(kq<<2)+3][row]=v.w;
        }
        #pragma unroll
        for(int i=0;i<4;i++){
            int j=t+(i<<8); int kq=j>>7, row=j&127;
            uint4 v=*(const uint4*)(Bsrc+(size_t)(bn+row)*512+kb+(kq<<3));
            Bp[(kq<<2)+0][row]=v.x; Bp[(kq<<2)+1][row]=v.y;
            Bp[(kq<<2)+2][row]=v.z; Bp[(kq<<2)+3][row]=v.w;
        }
        __syncthreads();
        #pragma unroll
        for(int kc=0;kc<4;kc++){
            int kpb=kc<<3;
            uint32_t af[4][4], bf[4][2];
            #pragma unroll
            for(int mt=0;mt<4;mt++){
                int mr=wm*64+mt*16+g;
                af[mt][0]=Ap[kpb+tig][mr];
                af[mt][1]=Ap[kpb+tig][mr+8];
                af[mt][2]=Ap[kpb+tig+4][mr];
                af[mt][3]=Ap[kpb+tig+4][mr+8];
            }
            #pragma unroll
            for(int nt=0;nt<4;nt++){
                int col=wn*32+nt*8+g;
                bf[nt][0]=Bp[kpb+tig][col];
                bf[nt][1]=Bp[kpb+tig+4][col];
            }
            #pragma unroll
            for(int mt=0;mt<4;mt++)
                #pragma unroll
                for(int nt=0;nt<4;nt++)
                    mma16816(acc[mt][nt], af[mt], bf[nt]);
        }
        __syncthreads();
    }

    #pragma unroll
    for(int mt=0;mt<4;mt++)
        #pragma unroll
        for(int nt=0;nt<4;nt++)
            #pragma unroll
            for(int ci=0;ci<4;ci++){
                int row=bm+wm*64+mt*16+g+((ci>>1)<<3);
                int col=bn+wn*32+nt*8+(tig<<1)+(ci&1);
                float val=acc[mt][nt][ci];
                if(mode==0){
                    int b_=row>>13, n=row&8191;
                    int s=col>>9, inner=col&511, h=inner>>6, d=inner&63;
                    size_t o=((size_t)((b_*NH+h)*NTOK+n))*DH+d;
                    if(s==0) g_q[o]=val*0.125f;
                    else if(s==1) g_k[o]=val;
                    else g_v[o]=val;
                } else {
                    size_t o=(size_t)row*DIMX+col;
                    outp[o]=xres[o]+bias[col]+val;
                }
            }
}

// ---- weight transpose + bf16 hi/lo split: W[K x N] -> BT[N][K] ----
__global__ void wtrans_kernel(const float* __restrict__ W,
                              __nv_bfloat16* __restrict__ BhiT, __nv_bfloat16* __restrict__ BloT,
                              int K, int N){
    __shared__ float tile[32][33];
    int k0=blockIdx.y*32, n0=blockIdx.x*32;
    int tx=threadIdx.x&31, ty=threadIdx.x>>5;
    #pragma unroll
    for(int i=0;i<32;i+=8) tile[ty+i][tx]=W[(size_t)(k0+ty+i)*N+n0+tx];
    __syncthreads();
    #pragma unroll
    for(int i=0;i<32;i+=8){
        int n=n0+ty+i, k=k0+tx;
        float v=tile[tx][ty+i];
        __nv_bfloat16 h=__float2bfloat16(v);
        BhiT[(size_t)n*K+k]=h;
        BloT[(size_t)n*K+k]=__float2bfloat16(v-__bfloat162float(h));
    }
}

// ---- attn -> bf16 hi/lo ----
__global__ void a2bf_kernel(){
    size_t i4=((size_t)blockIdx.x*256+threadIdx.x)*4;
    float4 v=*(const float4*)(g_attn+i4);
    float xs[4]={v.x,v.y,v.z,v.w};
    #pragma unroll
    for(int j=0;j<4;j++){
        __nv_bfloat16 h=__float2bfloat16(xs[j]);
        g_bhi[i4+j]=h;
        g_blo[i4+j]=__float2bfloat16(xs[j]-__bfloat162float(h));
    }
}

// ---- LayerNorm -> bf16 hi/lo ----
__global__ void ln_kernel(const float* __restrict__ x, const float* __restrict__ w,
                          const float* __restrict__ bp){
    int row=blockIdx.x, t=threadIdx.x;
    const float* xr=x+(size_t)row*DIMX;
    float v0=xr[t], v1=xr[t+256];
    float s=v0+v1, sq=v0*v0+v1*v1;
    __shared__ float r1[8], r2[8];
    #pragma unroll
    for(int o=16;o;o>>=1){ s+=__shfl_xor_sync(~0u,s,o); sq+=__shfl_xor_sync(~0u,sq,o); }
    if((t&31)==0){ r1[t>>5]=s; r2[t>>5]=sq; }
    __syncthreads();
    float ss=0, qq=0;
    #pragma unroll
    for(int i=0;i<8;i++){ ss+=r1[i]; qq+=r2[i]; }
    float mean=ss*(1.f/512.f);
    float rstd=rsqrtf(qq*(1.f/512.f)-mean*mean+1e-5f);
    float y0=(v0-mean)*rstd*w[t]+bp[t];
    float y1=(v1-mean)*rstd*w[t+256]+bp[t+256];
    __nv_bfloat16 h0=__float2bfloat16(y0), h1=__float2bfloat16(y1);
    size_t b=(size_t)row*DIMX;
    g_bhi[b+t]=h0;      g_blo[b+t]=__float2bfloat16(y0-__bfloat162float(h0));
    g_bhi[b+t+256]=h1;  g_blo[b+t+256]=__float2bfloat16(y1-__bfloat162float(h1));
}

// ================= fp32 SIMT cores (known-good) =================
__device__ __forceinline__ void loadA_kmajor(float (*As)[129], const float* __restrict__ Ag,
                                             int lda, int bm, int k0, int t){
    #pragma unroll
    for(int i=0;i<4;i++){
        int q=t+(i<<8); int r=q>>3; int kq=q&7;
        float4 v=*(const float4*)(Ag+(size_t)(bm+r)*lda+k0+(kq<<2));
        As[(kq<<2)+0][r]=v.x; As[(kq<<2)+1][r]=v.y;
        As[(kq<<2)+2][r]=v.z; As[(kq<<2)+3][r]=v.w;
    }
}
__device__ __forceinline__ void loadB_kn64(float (*Bs)[65], const float* __restrict__ Bg,
                                           int ldb, int bn, int k0, int t){
    #pragma unroll
    for(int i=0;i<2;i++){
        int q=t+(i<<8); int kk=q>>4; int cq=q&15;
        float4 v=*(const float4*)(Bg+(size_t)(k0+kk)*ldb+bn+(cq<<2));
        Bs[kk][(cq<<2)+0]=v.x; Bs[kk][(cq<<2)+1]=v.y;
        Bs[kk][(cq<<2)+2]=v.z; Bs[kk][(cq<<2)+3]=v.w;
    }
}
__device__ __forceinline__ void fma128(const float (*As)[129], const float (*Bs)[129],
                                       float acc[8][8], int tx, int ty){
    #pragma unroll
    for(int kk=0;kk<32;kk++){
        float a[8], b[8];
        #pragma unroll
        for(int i=0;i<8;i++) a[i]=As[kk][ty*8+i];
        #pragma unroll
        for(int j=0;j<8;j++) b[j]=Bs[kk][tx+(j<<4)];
        #pragma unroll
        for(int i=0;i<8;i++)
            #pragma unroll
            for(int j=0;j<8;j++) acc[i][j]+=a[i]*b[j];
    }
}
__device__ __forceinline__ void fma64(const float (*As)[129], const float (*Bs)[65],
                                      float acc[8][4], int tx, int ty){
    #pragma unroll
    for(int kk=0;kk<32;kk++){
        float a[8], b[4];
        #pragma unroll
        for(int i=0;i<8;i++) a[i]=As[kk][ty*8+i];
        #pragma unroll
        for(int j=0;j<4;j++) b[j]=Bs[kk][tx+(j<<4)];
        #pragma unroll
        for(int i=0;i<8;i++)
            #pragma unroll
            for(int j=0;j<4;j++) acc[i][j]+=a[i]*b[j];
    }
}
__device__ __forceinline__ void tile_fma32(const float (*As)[65], const float (*Bs)[65],
                                           float acc[4][4], int tx, int ty){
    #pragma unroll
    for(int kk=0;kk<32;kk++){
        float a[4], b[4];
        #pragma unroll
        for(int i=0;i<4;i++) a[i]=As[kk][ty*4+i];
        #pragma unroll
        for(int j=0;j<4;j++) b[j]=Bs[kk][tx+16*j];
        #pragma unroll
        for(int i=0;i<4;i++)
            #pragma unroll
            for(int j=0;j<4;j++) acc[i][j]+=a[i]*b[j];
    }
}

__global__ void landmark_kernel(){
    int blk=blockIdx.x, bh=blk>>8, m=blk&255, d=threadIdx.x;
    const float* qp=g_q+((size_t)(bh*NTOK+m*32))*DH+d;
    const float* kp=g_k+((size_t)(bh*NTOK+m*32))*DH+d;
    float sq=0,sk=0;
    #pragma unroll
    for(int j=0;j<32;j++){ sq+=qp[(size_t)j*DH]; sk+=kp[(size_t)j*DH]; }
    g_ql[(bh*ML+m)*DH+d]=sq*(1.f/32.f);
    g_kl[(bh*ML+m)*DH+d]=sk*(1.f/32.f);
}

__global__ void sim_kernel(const float* __restrict__ Abase, const float* __restrict__ Bbase,
                           float* __restrict__ Cbase, size_t aBH, size_t bBH, size_t cBH, int ldC){
    __shared__ float As[32][129], Bs[32][129];
    int t=threadIdx.x, tx=t&15, ty=t>>4;
    int bh=blockIdx.z;
    int bn=blockIdx.x*128, bm=blockIdx.y*128;
    const float* A=Abase+(size_t)bh*aBH;
    const float* B=Bbase+(size_t)bh*bBH;
    float* C=Cbase+(size_t)bh*cBH;
    float acc[8][8]={};
    for(int k0=0;k0<64;k0+=32){
        loadA_kmajor(As, A, DH, bm, k0, t);
        loadA_kmajor(Bs, B, DH, bn, k0, t);
        __syncthreads();
        fma128(As,Bs,acc,tx,ty);
        __syncthreads();
    }
    #pragma unroll
    for(int i=0;i<8;i++)
        #pragma unroll
        for(int j=0;j<8;j++)
            C[(size_t)(bm+ty*8+i)*ldC+bn+tx+(j<<4)]=acc[i][j];
}

__global__ void softmax256_kernel(float* __restrict__ base){
    int w=threadIdx.x>>5, lane=threadIdx.x&31;
    size_t row=(size_t)blockIdx.x*8+w;
    float* p=base+row*ML;
    float4 v0=*(float4*)(p+lane*8);
    float4 v1=*(float4*)(p+lane*8+4);
    float mx=fmaxf(fmaxf(fmaxf(v0.x,v0.y),fmaxf(v0.z,v0.w)),
                   fmaxf(fmaxf(v1.x,v1.y),fmaxf(v1.z,v1.w)));
    #pragma unroll
    for(int o=16;o;o>>=1) mx=fmaxf(mx,__shfl_xor_sync(~0u,mx,o));
    v0.x=__expf(v0.x-mx); v0.y=__expf(v0.y-mx); v0.z=__expf(v0.z-mx); v0.w=__expf(v0.w-mx);
    v1.x=__expf(v1.x-mx); v1.y=__expf(v1.y-mx); v1.z=__expf(v1.z-mx); v1.w=__expf(v1.w-mx);
    float s=v0.x+v0.y+v0.z+v0.w+v1.x+v1.y+v1.z+v1.w;
    #pragma unroll
    for(int o=16;o;o>>=1) s+=__shfl_xor_sync(~0u,s,o);
    float inv=1.f/s;
    v0.x*=inv; v0.y*=inv; v0.z*=inv; v0.w*=inv;
    v1.x*=inv; v1.y*=inv; v1.z*=inv; v1.w*=inv;
    *(float4*)(p+lane*8)=v0;
    *(float4*)(p+lane*8+4)=v1;
}

__global__ void scal_reset_kernel(){ g_scal[0]=0.f; g_scal[1]=0.f; }

__global__ void pinv_sums_kernel(){
    int bh=blockIdx.x, t=threadIdx.x;
    const float* A=g_a2+((size_t)bh<<16);
    float rs=0, cs=0;
    const float4* Ar=(const float4*)(A+(size_t)t*ML);
    #pragma unroll
    for(int j=0;j<64;j++){ float4 v=Ar[j]; rs+=fabsf(v.x)+fabsf(v.y)+fabsf(v.z)+fabsf(v.w); }
    for(int j=0;j<ML;j++) cs+=fabsf(A[(size_t)j*ML+t]);
    #pragma unroll
    for(int o=16;o;o>>=1){ rs=fmaxf(rs,__shfl_xor_sync(~0u,rs,o)); cs=fmaxf(cs,__shfl_xor_sync(~0u,cs,o)); }
    __shared__ float r1[8], r2[8];
    if((t&31)==0){ r1[t>>5]=rs; r2[t>>5]=cs; }
    __syncthreads();
    if(t==0){
        float m1=r1[0], m2=r2[0];
        #pragma unroll
        for(int k=1;k<8;k++){ m1=fmaxf(m1,r1[k]); m2=fmaxf(m2,r2[k]); }
        atomicMax((int*)&g_scal[0], __float_as_int(m1));
        atomicMax((int*)&g_scal[1], __float_as_int(m2));
    }
}

__global__ void zinit_kernel(){
    int e=blockIdx.x*256+threadIdx.x;
    float inv=1.f/(g_scal[0]*g_scal[1]);
    int bh=e>>16, r=(e>>8)&255, c=e&255;
    g_z0[e]=g_a2[(bh<<16)+(c<<8)+r]*inv;
}

__global__ void mm256_kernel(const float* __restrict__ Ag, const float* __restrict__ Bg,
                             float* __restrict__ Cg, float cdiag, float alpha){
    int bh=blockIdx.x;
    const float* A=Ag+((size_t)bh<<16);
    const float* B=Bg+((size_t)bh<<16);
    float* C=Cg+((size_t)bh<<16);
    int bm=blockIdx.y*64, bn=blockIdx.z*64;
    __shared__ float As[32][65], Bs[32][65];
    int t=threadIdx.x, tx=t&15, ty=t>>4;
    float acc[4][4]={};
    for(int k0=0;k0<256;k0+=32){
        #pragma unroll
        for(int i=0;i<8;i++){ int idx=t+(i<<8); int r=idx>>5,kk=idx&31;
            As[kk][r]=A[(size_t)(bm+r)*256+k0+kk]; }
        #pragma unroll
        for(int i=0;i<8;i++){ int idx=t+(i<<8); int kk=idx>>6,c=idx&63;
            int gk=k0+kk, gc=bn+c;
            float bv=B[(size_t)gk*256+gc];
            Bs[kk][c]=(gk==gc)?(cdiag-bv):(-bv); }
        __syncthreads();
        tile_fma32(As,Bs,acc,tx,ty);
        __syncthreads();
    }
    #pragma unroll
    for(int i=0;i<4;i++)
        #pragma unroll
        for(int j=0;j<4;j++)
            C[(size_t)(bm+ty*4+i)*256+bn+tx+(j<<4)]=alpha*acc[i][j];
}

__global__ void softmax3_kernel(){
    int row=blockIdx.x, t=threadIdx.x;
    float* p=g_sim3+(size_t)row*NTOK;
    float v[32], mx=-3.0e38f;
    #pragma unroll
    for(int i=0;i<32;i++){ v[i]=p[t+(i<<8)]; mx=fmaxf(mx,v[i]); }
    __shared__ float red[8];
    #pragma unroll
    for(int o=16;o;o>>=1) mx=fmaxf(mx,__shfl_xor_sync(~0u,mx,o));
    if((t&31)==0) red[t>>5]=mx;
    __syncthreads();
    mx=red[0];
    #pragma unroll
    for(int k=1;k<8;k++) mx=fmaxf(mx,red[k]);
    float s=0;
    #pragma unroll
    for(int i=0;i<32;i++){ v[i]=__expf(v[i]-mx); s+=v[i]; }
    #pragma unroll
    for(int o=16;o;o>>=1) s+=__shfl_xor_sync(~0u,s,o);
    __syncthreads();
    if((t&31)==0) red[t>>5]=s;
    __syncthreads();
    s=0;
    #pragma unroll
    for(int k=0;k<8;k++) s+=red[k];
    float inv=1.f/s;
    #pragma unroll
    for(int i=0;i<32;i++) p[t+(i<<8)]=v[i]*inv;
}

__global__ void a3v_kernel(){
    __shared__ float As[32][129], Bs[32][65];
    int ksp=blockIdx.x, bm=blockIdx.y*128, bh=blockIdx.z;
    int t=threadIdx.x, tx=t&15, ty=t>>4;
    float acc[8][4]={};
    const float* Ap=g_sim3+(size_t)(bh*ML)*NTOK;
    const float* Vp=g_v+(size_t)bh*NTOK*DH;
    int kbeg=ksp*1024;
    for(int k0=kbeg;k0<kbeg+1024;k0+=32){
        loadA_kmajor(As, Ap, NTOK, bm, k0, t);
        loadB_kn64(Bs, Vp, DH, 0, k0, t);
        __syncthreads();
        fma64(As,Bs,acc,tx,ty);
        __syncthreads();
    }
    #pragma unroll
    for(int i=0;i<8;i++)
        #pragma unroll
        for(int j=0;j<4;j++)
            g_a3vp[(size_t)(ksp*BHN+bh)*ML*DH+(bm+ty*8+i)*DH+tx+(j<<4)]=acc[i][j];
}

__global__ void a3v_reduce_kernel(){
    int e=blockIdx.x*256+threadIdx.x;
    float s=0;
    #pragma unroll
    for(int k=0;k<8;k++) s+=g_a3vp[(size_t)k*BHN*ML*DH+e];
    g_a3v[e]=s;
}

__global__ void z2_kernel(){
    __shared__ float As[32][129], Bs[32][65];
    int bm=blockIdx.x*128, bh=blockIdx.y;
    const float* A=g_z0+((size_t)bh<<16);
    const float* Bp=g_a3v+(size_t)bh*ML*DH;
    int t=threadIdx.x, tx=t&15, ty=t>>4;
    float acc[8][4]={};
    for(int k0=0;k0<256;k0+=32){
        loadA_kmajor(As, A, ML, bm, k0, t);
        loadB_kn64(Bs, Bp, DH, 0, k0, t);
        __syncthreads();
        fma64(As,Bs,acc,tx,ty);
        __syncthreads();
    }
    #pragma unroll
    for(int i=0;i<8;i++)
        #pragma unroll
        for(int j=0;j<4;j++)
            g_Z2[(size_t)bh*ML*DH+(bm+ty*8+i)*DH+tx+(j<<4)]=acc[i][j];
}

__global__ void conv_kernel(const float* __restrict__ cw){
    int idx=blockIdx.x*256+threadIdx.x;
    int d=idx&63, n=(idx>>6)&8191, bh=idx>>19;
    int h=bh&7;
    const float* vp=g_v+(size_t)bh*NTOK*DH+d;
    float s=0;
    #pragma unroll
    for(int kk=0;kk<33;kk++){
        int j=n+kk-16;
        if(j>=0 && j<NTOK) s+=cw[h*33+kk]*vp[(size_t)j*DH];
    }
    g_attn[((size_t)((bh>>3)*NTOK+n))*DIMX+h*64+d]=s;
}

__global__ void a1z2_kernel(){
    __shared__ float As[32][129], Bs[32][65];
    int bm=blockIdx.x*128, bh=blockIdx.y;
    const float* A=g_sim3+(size_t)bh*NTOK*ML;
    const float* Bp=g_Z2+(size_t)bh*ML*DH;
    int t=threadIdx.x, tx=t&15, ty=t>>4;
    float acc[8][4]={};
    for(int k0=0;k0<256;k0+=32){
        loadA_kmajor(As, A, ML, bm, k0, t);
        loadB_kn64(Bs, Bp, DH, 0, k0, t);
        __syncthreads();
        fma64(As,Bs,acc,tx,ty);
        __syncthreads();
    }
    int b=bh>>3, h=bh&7;
    #pragma unroll
    for(int i=0;i<8;i++){
        size_t base=((size_t)(b*NTOK+bm+ty*8+i))*DIMX+h*64;
        #pragma unroll
        for(int j=0;j<4;j++)
            g_attn[base+tx+(j<<4)]+=acc[i][j];
    }
}

extern "C" void kernel_launch(void* const* d_in, const int* in_sizes, int n_in,
                              void* d_out, int out_size){
    const float* x    = (const float*)d_in[0];
    const float* ln_w = (const float*)d_in[2];
    const float* ln_b = (const float*)d_in[3];
    const float* wqkv = (const float*)d_in[4];
    const float* wout = (const float*)d_in[5];
    const float* bout = (const float*)d_in[6];
    const float* cw   = (const float*)d_in[7];
    float* out = (float*)d_out;

    float *z0,*z1,*a2p,*xz,*t1,*t2,*qlp,*klp,*qp,*kp,*sim3p;
    __nv_bfloat16 *bhi,*blo,*wqhi,*wqlo,*wohi,*wolo;
    cudaGetSymbolAddress((void**)&z0, g_z0);
    cudaGetSymbolAddress((void**)&z1, g_z1);
    cudaGetSymbolAddress((void**)&a2p, g_a2);
    cudaGetSymbolAddress((void**)&xz, g_xz);
    cudaGetSymbolAddress((void**)&t1, g_t1);
    cudaGetSymbolAddress((void**)&t2, g_t2);
    cudaGetSymbolAddress((void**)&qlp, g_ql);
    cudaGetSymbolAddress((void**)&klp, g_kl);
    cudaGetSymbolAddress((void**)&qp, g_q);
    cudaGetSymbolAddress((void**)&kp, g_k);
    cudaGetSymbolAddress((void**)&sim3p, g_sim3);
    cudaGetSymbolAddress((void**)&bhi, g_bhi);
    cudaGetSymbolAddress((void**)&blo, g_blo);
    cudaGetSymbolAddress((void**)&wqhi, g_wqhi);
    cudaGetSymbolAddress((void**)&wqlo, g_wqlo);
    cudaGetSymbolAddress((void**)&wohi, g_wohi);
    cudaGetSymbolAddress((void**)&wolo, g_wolo);

    wtrans_kernel<<<dim3(48,16), 256>>>(wqkv, wqhi, wqlo, 512, 1536);
    wtrans_kernel<<<dim3(16,16), 256>>>(wout, wohi, wolo, 512, 512);

    ln_kernel<<<BB*NTOK, 256>>>(x, ln_w, ln_b);

    bf_gemm<<<dim3(12,128), 256>>>(bhi, blo, wqhi, wqlo, 0, nullptr, nullptr, nullptr);

    landmark_kernel<<<BHN*ML, 64>>>();

    sim_kernel<<<dim3(2,2,BHN), 256>>>(qlp, klp, a2p,
        (size_t)ML*DH, (size_t)ML*DH, (size_t)ML*ML, ML);
    softmax256_kernel<<<BHN*ML/8, 256>>>(a2p);

    scal_reset_kernel<<<1,1>>>();
    pinv_sums_kernel<<<BHN, 256>>>();
    zinit_kernel<<<4096, 256>>>();

    float* zc=z0; float* za=z1;
    for(int it=0; it<6; it++){
        mm256_kernel<<<dim3(BHN,4,4),256>>>(a2p, zc, xz, 0.f, -1.f);
        mm256_kernel<<<dim3(BHN,4,4),256>>>(xz, xz, t1, 7.f, 1.f);
        mm256_kernel<<<dim3(BHN,4,4),256>>>(xz, t1, t2, 15.f, 1.f);
        mm256_kernel<<<dim3(BHN,4,4),256>>>(zc, t2, za, 13.f, 0.25f);
        float* tmp=zc; zc=za; za=tmp;
    }

    sim_kernel<<<dim3(64,2,BHN), 256>>>(qlp, kp, sim3p,
        (size_t)ML*DH, (size_t)NTOK*DH, (size_t)ML*NTOK, NTOK);
    softmax3_kernel<<<BHN*ML, 256>>>();
    a3v_kernel<<<dim3(8,2,BHN), 256>>>();
    a3v_reduce_kernel<<<1024, 256>>>();
    z2_kernel<<<dim3(2,BHN), 256>>>();
    conv_kernel<<<32768, 256>>>(cw);

    sim_kernel<<<dim3(2,64,BHN), 256>>>(qp, klp, sim3p,
        (size_t)NTOK*DH, (size_t)ML*DH, (size_t)NTOK*ML, ML);
    softmax256_kernel<<<BHN*NTOK/8, 256>>>(sim3p);
    a1z2_kernel<<<dim3(64,BHN), 256>>>();

    a2bf_kernel<<<8192, 256>>>();
    bf_gemm<<<dim3(4,128), 256>>>(bhi, blo, wohi, wolo, 1, x, bout, out);
}

// round 11
// speedup vs baseline: 1.1451x; 1.0409x over previous
#include <cuda_runtime.h>
#include <cuda_bf16.h>
#include <math.h>
#include <stdint.h>

#define BB 2
#define NTOK 8192
#define DIMX 512
#define NH 8
#define DH 64
#define ML 256
#define BHN 16

__device__ float g_q [BHN*NTOK*DH];
__device__ float g_k [BHN*NTOK*DH];
__device__ float g_v [BHN*NTOK*DH];
__device__ float g_ql[BHN*ML*DH];
__device__ float g_kl[BHN*ML*DH];
__device__ float g_a2[BHN*ML*ML];
__device__ float g_z0[BHN*ML*ML];
__device__ float g_z1[BHN*ML*ML];
__device__ float g_xz[BHN*ML*ML];
__device__ float g_t1[BHN*ML*ML];
__device__ float g_t2[BHN*ML*ML];
__device__ float g_sim3[(size_t)BHN*ML*NTOK];
__device__ float g_a3vp[8*BHN*ML*DH];
__device__ float g_a3v [BHN*ML*DH];
__device__ float g_Z2  [BHN*ML*DH];
__device__ float g_attn[BB*NTOK*DIMX];
__device__ float g_scal[2];
__device__ __nv_bfloat16 g_bhi[BB*NTOK*DIMX];
__device__ __nv_bfloat16 g_blo[BB*NTOK*DIMX];
__device__ __nv_bfloat16 g_wqhi[1536*512];
__device__ __nv_bfloat16 g_wqlo[1536*512];
__device__ __nv_bfloat16 g_wohi[512*512];
__device__ __nv_bfloat16 g_wolo[512*512];

// ================= bf16 mma.sync =================
__device__ __forceinline__ void mma16816(float* c, const uint32_t* a, const uint32_t* b){
    asm volatile("mma.sync.aligned.m16n8k16.row.col.f32.bf16.bf16.f32 "
        "{%0,%1,%2,%3},{%4,%5,%6,%7},{%8,%9},{%0,%1,%2,%3};"
        : "+f"(c[0]),"+f"(c[1]),"+f"(c[2]),"+f"(c[3])
        : "r"(a[0]),"r"(a[1]),"r"(a[2]),"r"(a[3]),"r"(b[0]),"r"(b[1]));
}

// bf16-split GEMM: C[128x128] = A @ B^T over Keff = 3*512.
// 4 warps, warp tile 64x64 (2x2 warp grid) -> LDS:MMA wavefronts 1:1.
__global__ void __launch_bounds__(128) bf_gemm(
    const __nv_bfloat16* __restrict__ Ahi, const __nv_bfloat16* __restrict__ Alo,
    const __nv_bfloat16* __restrict__ BhiT, const __nv_bfloat16* __restrict__ BloT,
    int mode, const float* __restrict__ xres, const float* __restrict__ bias,
    float* __restrict__ outp)
{
    __shared__ uint32_t Ap[32][136];
    __shared__ uint32_t Bp[32][136];
    int t=threadIdx.x, lane=t&31, wid=t>>5;         // 4 warps
    int g=lane>>2, tig=lane&3;
    int wm=wid&1, wn=wid>>1;                        // 2x2 warp grid
    int bn=blockIdx.x*128, bm=blockIdx.y*128;
    float acc[4][8][4];
    #pragma unroll
    for(int a=0;a<4;a++)
        #pragma unroll
        for(int b=0;b<8;b++)
            #pragma unroll
            for(int c=0;c<4;c++) acc[a][b][c]=0.f;

    for(int blk=0;blk<24;blk++){
        int seg=blk>>3, kb=(blk&7)<<6;
        const __nv_bfloat16* Asrc=(seg<2)?Ahi:Alo;
        const __nv_bfloat16* Bsrc=(seg==1)?BloT:BhiT;
        #pragma unroll
        for(int i=0;i<8;i++){
            int j=t+(i<<7); int kq=j>>7, row=j&127;
            uint4 v=*(const uint4*)(Asrc+(size_t)(bm+row)*512+kb+(kq<<3));
            Ap[(kq<<2)+0][row]=v.x; Ap[(kq<<2)+1][row]=v.y;
            Ap[(kq<<2)+2][row]=v.z; Ap[(kq<<2)+3][row]=v.w;
        }
        #pragma unroll
        for(int i=0;i<8;i++){
            int j=t+(i<<7); int kq=j>>7, row=j&127;
            uint4 v=*(const uint4*)(Bsrc+(size_t)(bn+row)*512+kb+(kq<<3));
            Bp[(kq<<2)+0][row]=v.x; Bp[(kq<<2)+1][row]=v.y;
            Bp[(kq<<2)+2][row]=v.z; Bp[(kq<<2)+3][row]=v.w;
        }
        __syncthreads();
        #pragma unroll
        for(int kc=0;kc<4;kc++){
            int kpb=kc<<3;
            uint32_t af[4][4], bfr[8][2];
            #pragma unroll
            for(int mt=0;mt<4;mt++){
                int mr=wm*64+mt*16+g;
                af[mt][0]=Ap[kpb+tig][mr];
                af[mt][1]=Ap[kpb+tig][mr+8];
                af[mt][2]=Ap[kpb+tig+4][mr];
                af[mt][3]=Ap[kpb+tig+4][mr+8];
            }
            #pragma unroll
            for(int nt=0;nt<8;nt++){
                int col=wn*64+nt*8+g;
                bfr[nt][0]=Bp[kpb+tig][col];
                bfr[nt][1]=Bp[kpb+tig+4][col];
            }
            #pragma unroll
            for(int mt=0;mt<4;mt++)
                #pragma unroll
                for(int nt=0;nt<8;nt++)
                    mma16816(acc[mt][nt], af[mt], bfr[nt]);
        }
        __syncthreads();
    }

    #pragma unroll
    for(int mt=0;mt<4;mt++)
        #pragma unroll
        for(int nt=0;nt<8;nt++)
            #pragma unroll
            for(int ci=0;ci<4;ci++){
                int row=bm+wm*64+mt*16+g+((ci>>1)<<3);
                int col=bn+wn*64+nt*8+(tig<<1)+(ci&1);
                float val=acc[mt][nt][ci];
                if(mode==0){
                    int b_=row>>13, n=row&8191;
                    int s=col>>9, inner=col&511, h=inner>>6, d=inner&63;
                    size_t o=((size_t)((b_*NH+h)*NTOK+n))*DH+d;
                    if(s==0) g_q[o]=val*0.125f;
                    else if(s==1) g_k[o]=val;
                    else g_v[o]=val;
                } else {
                    size_t o=(size_t)row*DIMX+col;
                    outp[o]=xres[o]+bias[col]+val;
                }
            }
}

// ---- weight transpose + bf16 hi/lo split ----
__global__ void wtrans_kernel(const float* __restrict__ W,
                              __nv_bfloat16* __restrict__ BhiT, __nv_bfloat16* __restrict__ BloT,
                              int K, int N){
    __shared__ float tile[32][33];
    int k0=blockIdx.y*32, n0=blockIdx.x*32;
    int tx=threadIdx.x&31, ty=threadIdx.x>>5;
    #pragma unroll
    for(int i=0;i<32;i+=8) tile[ty+i][tx]=W[(size_t)(k0+ty+i)*N+n0+tx];
    __syncthreads();
    #pragma unroll
    for(int i=0;i<32;i+=8){
        int n=n0+ty+i, k=k0+tx;
        float v=tile[tx][ty+i];
        __nv_bfloat16 h=__float2bfloat16(v);
        BhiT[(size_t)n*K+k]=h;
        BloT[(size_t)n*K+k]=__float2bfloat16(v-__bfloat162float(h));
    }
}

__global__ void a2bf_kernel(){
    size_t i4=((size_t)blockIdx.x*256+threadIdx.x)*4;
    float4 v=*(const float4*)(g_attn+i4);
    float xs[4]={v.x,v.y,v.z,v.w};
    #pragma unroll
    for(int j=0;j<4;j++){
        __nv_bfloat16 h=__float2bfloat16(xs[j]);
        g_bhi[i4+j]=h;
        g_blo[i4+j]=__float2bfloat16(xs[j]-__bfloat162float(h));
    }
}

__global__ void ln_kernel(const float* __restrict__ x, const float* __restrict__ w,
                          const float* __restrict__ bp){
    int row=blockIdx.x, t=threadIdx.x;
    const float* xr=x+(size_t)row*DIMX;
    float v0=xr[t], v1=xr[t+256];
    float s=v0+v1, sq=v0*v0+v1*v1;
    __shared__ float r1[8], r2[8];
    #pragma unroll
    for(int o=16;o;o>>=1){ s+=__shfl_xor_sync(~0u,s,o); sq+=__shfl_xor_sync(~0u,sq,o); }
    if((t&31)==0){ r1[t>>5]=s; r2[t>>5]=sq; }
    __syncthreads();
    float ss=0, qq=0;
    #pragma unroll
    for(int i=0;i<8;i++){ ss+=r1[i]; qq+=r2[i]; }
    float mean=ss*(1.f/512.f);
    float rstd=rsqrtf(qq*(1.f/512.f)-mean*mean+1e-5f);
    float y0=(v0-mean)*rstd*w[t]+bp[t];
    float y1=(v1-mean)*rstd*w[t+256]+bp[t+256];
    __nv_bfloat16 h0=__float2bfloat16(y0), h1=__float2bfloat16(y1);
    size_t b=(size_t)row*DIMX;
    g_bhi[b+t]=h0;      g_blo[b+t]=__float2bfloat16(y0-__bfloat162float(h0));
    g_bhi[b+t+256]=h1;  g_blo[b+t+256]=__float2bfloat16(y1-__bfloat162float(h1));
}

// ================= fp32 SIMT cores =================
__device__ __forceinline__ void loadA_kmajor(float (*As)[129], const float* __restrict__ Ag,
                                             int lda, int bm, int k0, int t){
    #pragma unroll
    for(int i=0;i<4;i++){
        int q=t+(i<<8); int r=q>>3; int kq=q&7;
        float4 v=*(const float4*)(Ag+(size_t)(bm+r)*lda+k0+(kq<<2));
        As[(kq<<2)+0][r]=v.x; As[(kq<<2)+1][r]=v.y;
        As[(kq<<2)+2][r]=v.z; As[(kq<<2)+3][r]=v.w;
    }
}
__device__ __forceinline__ void loadB_kn64(float (*Bs)[65], const float* __restrict__ Bg,
                                           int ldb, int bn, int k0, int t){
    #pragma unroll
    for(int i=0;i<2;i++){
        int q=t+(i<<8); int kk=q>>4; int cq=q&15;
        float4 v=*(const float4*)(Bg+(size_t)(k0+kk)*ldb+bn+(cq<<2));
        Bs[kk][(cq<<2)+0]=v.x; Bs[kk][(cq<<2)+1]=v.y;
        Bs[kk][(cq<<2)+2]=v.z; Bs[kk][(cq<<2)+3]=v.w;
    }
}
__device__ __forceinline__ void fma128(const float (*As)[129], const float (*Bs)[129],
                                       float acc[8][8], int tx, int ty){
    #pragma unroll
    for(int kk=0;kk<32;kk++){
        float a[8], b[8];
        #pragma unroll
        for(int i=0;i<8;i++) a[i]=As[kk][ty*8+i];
        #pragma unroll
        for(int j=0;j<8;j++) b[j]=Bs[kk][tx+(j<<4)];
        #pragma unroll
        for(int i=0;i<8;i++)
            #pragma unroll
            for(int j=0;j<8;j++) acc[i][j]+=a[i]*b[j];
    }
}
__device__ __forceinline__ void fma64(const float (*As)[129], const float (*Bs)[65],
                                      float acc[8][4], int tx, int ty){
    #pragma unroll
    for(int kk=0;kk<32;kk++){
        float a[8], b[4];
        #pragma unroll
        for(int i=0;i<8;i++) a[i]=As[kk][ty*8+i];
        #pragma unroll
        for(int j=0;j<4;j++) b[j]=Bs[kk][tx+(j<<4)];
        #pragma unroll
        for(int i=0;i<8;i++)
            #pragma unroll
            for(int j=0;j<4;j++) acc[i][j]+=a[i]*b[j];
    }
}

__global__ void landmark_kernel(){
    int blk=blockIdx.x, bh=blk>>8, m=blk&255, d=threadIdx.x;
    const float* qp=g_q+((size_t)(bh*NTOK+m*32))*DH+d;
    const float* kp=g_k+((size_t)(bh*NTOK+m*32))*DH+d;
    float sq=0,sk=0;
    #pragma unroll
    for(int j=0;j<32;j++){ sq+=qp[(size_t)j*DH]; sk+=kp[(size_t)j*DH]; }
    g_ql[(bh*ML+m)*DH+d]=sq*(1.f/32.f);
    g_kl[(bh*ML+m)*DH+d]=sk*(1.f/32.f);
}

__global__ void sim_kernel(const float* __restrict__ Abase, const float* __restrict__ Bbase,
                           float* __restrict__ Cbase, size_t aBH, size_t bBH, size_t cBH, int ldC){
    __shared__ float As[32][129], Bs[32][129];
    int t=threadIdx.x, tx=t&15, ty=t>>4;
    int bh=blockIdx.z;
    int bn=blockIdx.x*128, bm=blockIdx.y*128;
    const float* A=Abase+(size_t)bh*aBH;
    const float* B=Bbase+(size_t)bh*bBH;
    float* C=Cbase+(size_t)bh*cBH;
    float acc[8][8]={};
    for(int k0=0;k0<64;k0+=32){
        loadA_kmajor(As, A, DH, bm, k0, t);
        loadA_kmajor(Bs, B, DH, bn, k0, t);
        __syncthreads();
        fma128(As,Bs,acc,tx,ty);
        __syncthreads();
    }
    #pragma unroll
    for(int i=0;i<8;i++)
        #pragma unroll
        for(int j=0;j<8;j++)
            C[(size_t)(bm+ty*8+i)*ldC+bn+tx+(j<<4)]=acc[i][j];
}

__global__ void softmax256_kernel(float* __restrict__ base){
    int w=threadIdx.x>>5, lane=threadIdx.x&31;
    size_t row=(size_t)blockIdx.x*8+w;
    float* p=base+row*ML;
    float4 v0=*(float4*)(p+lane*8);
    float4 v1=*(float4*)(p+lane*8+4);
    float mx=fmaxf(fmaxf(fmaxf(v0.x,v0.y),fmaxf(v0.z,v0.w)),
                   fmaxf(fmaxf(v1.x,v1.y),fmaxf(v1.z,v1.w)));
    #pragma unroll
    for(int o=16;o;o>>=1) mx=fmaxf(mx,__shfl_xor_sync(~0u,mx,o));
    v0.x=__expf(v0.x-mx); v0.y=__expf(v0.y-mx); v0.z=__expf(v0.z-mx); v0.w=__expf(v0.w-mx);
    v1.x=__expf(v1.x-mx); v1.y=__expf(v1.y-mx); v1.z=__expf(v1.z-mx); v1.w=__expf(v1.w-mx);
    float s=v0.x+v0.y+v0.z+v0.w+v1.x+v1.y+v1.z+v1.w;
    #pragma unroll
    for(int o=16;o;o>>=1) s+=__shfl_xor_sync(~0u,s,o);
    float inv=1.f/s;
    v0.x*=inv; v0.y*=inv; v0.z*=inv; v0.w*=inv;
    v1.x*=inv; v1.y*=inv; v1.z*=inv; v1.w*=inv;
    *(float4*)(p+lane*8)=v0;
    *(float4*)(p+lane*8+4)=v1;
}

__global__ void scal_reset_kernel(){ g_scal[0]=0.f; g_scal[1]=0.f; }

__global__ void pinv_sums_kernel(){
    int bh=blockIdx.x, t=threadIdx.x;
    const float* A=g_a2+((size_t)bh<<16);
    float rs=0, cs=0;
    const float4* Ar=(const float4*)(A+(size_t)t*ML);
    #pragma unroll
    for(int j=0;j<64;j++){ float4 v=Ar[j]; rs+=fabsf(v.x)+fabsf(v.y)+fabsf(v.z)+fabsf(v.w); }
    for(int j=0;j<ML;j++) cs+=fabsf(A[(size_t)j*ML+t]);
    #pragma unroll
    for(int o=16;o;o>>=1){ rs=fmaxf(rs,__shfl_xor_sync(~0u,rs,o)); cs=fmaxf(cs,__shfl_xor_sync(~0u,cs,o)); }
    __shared__ float r1[8], r2[8];
    if((t&31)==0){ r1[t>>5]=rs; r2[t>>5]=cs; }
    __syncthreads();
    if(t==0){
        float m1=r1[0], m2=r2[0];
        #pragma unroll
        for(int k=1;k<8;k++){ m1=fmaxf(m1,r1[k]); m2=fmaxf(m2,r2[k]); }
        atomicMax((int*)&g_scal[0], __float_as_int(m1));
        atomicMax((int*)&g_scal[1], __float_as_int(m2));
    }
}

__global__ void zinit_kernel(){
    int e=blockIdx.x*256+threadIdx.x;
    float inv=1.f/(g_scal[0]*g_scal[1]);
    int bh=e>>16, r=(e>>8)&255, c=e&255;
    g_z0[e]=g_a2[(bh<<16)+(c<<8)+r]*inv;
}

// ---- batched 256^3: C = alpha * A @ (cdiag*I - B), 64x64 tile, 8x4 microtile, 128 thr ----
__global__ void __launch_bounds__(128) mm256_kernel(
        const float* __restrict__ Ag, const float* __restrict__ Bg,
        float* __restrict__ Cg, float cdiag, float alpha){
    int bh=blockIdx.x;
    const float* A=Ag+((size_t)bh<<16);
    const float* B=Bg+((size_t)bh<<16);
    float* C=Cg+((size_t)bh<<16);
    int bm=blockIdx.y*64, bn=blockIdx.z*64;
    __shared__ float As[32][65], Bs[32][65];
    int t=threadIdx.x, tx=t&15, ty=t>>4;   // ty 0..7
    float acc[8][4]={};
    for(int k0=0;k0<256;k0+=32){
        #pragma unroll
        for(int i=0;i<4;i++){
            int j=t+(i<<7); int r=j>>3, kq=j&7;
            float4 v=*(const float4*)(A+(size_t)(bm+r)*256+k0+(kq<<2));
            As[(kq<<2)+0][r]=v.x; As[(kq<<2)+1][r]=v.y;
            As[(kq<<2)+2][r]=v.z; As[(kq<<2)+3][r]=v.w;
        }
        #pragma unroll
        for(int i=0;i<16;i++){
            int j=t+(i<<7); int kk=j>>6, c=j&63;
            int gk=k0+kk, gc=bn+c;
            float bv=B[(size_t)gk*256+gc];
            Bs[kk][c]=(gk==gc)?(cdiag-bv):(-bv);
        }
        __syncthreads();
        #pragma unroll
        for(int kk=0;kk<32;kk++){
            float a[8], b[4];
            #pragma unroll
            for(int i=0;i<8;i++) a[i]=As[kk][ty*8+i];
            #pragma unroll
            for(int j=0;j<4;j++) b[j]=Bs[kk][tx+(j<<4)];
            #pragma unroll
            for(int i=0;i<8;i++)
                #pragma unroll
                for(int j=0;j<4;j++) acc[i][j]+=a[i]*b[j];
        }
        __syncthreads();
    }
    #pragma unroll
    for(int i=0;i<8;i++)
        #pragma unroll
        for(int j=0;j<4;j++)
            C[(size_t)(bm+ty*8+i)*256+bn+tx+(j<<4)]=alpha*acc[i][j];
}

__global__ void softmax3_kernel(){
    int row=blockIdx.x, t=threadIdx.x;
    float* p=g_sim3+(size_t)row*NTOK;
    float v[32], mx=-3.0e38f;
    #pragma unroll
    for(int i=0;i<32;i++){ v[i]=p[t+(i<<8)]; mx=fmaxf(mx,v[i]); }
    __shared__ float red[8];
    #pragma unroll
    for(int o=16;o;o>>=1) mx=fmaxf(mx,__shfl_xor_sync(~0u,mx,o));
    if((t&31)==0) red[t>>5]=mx;
    __syncthreads();
    mx=red[0];
    #pragma unroll
    for(int k=1;k<8;k++) mx=fmaxf(mx,red[k]);
    float s=0;
    #pragma unroll
    for(int i=0;i<32;i++){ v[i]=__expf(v[i]-mx); s+=v[i]; }
    #pragma unroll
    for(int o=16;o;o>>=1) s+=__shfl_xor_sync(~0u,s,o);
    __syncthreads();
    if((t&31)==0) red[t>>5]=s;
    __syncthreads();
    s=0;
    #pragma unroll
    for(int k=0;k<8;k++) s+=red[k];
    float inv=1.f/s;
    #pragma unroll
    for(int i=0;i<32;i++) p[t+(i<<8)]=v[i]*inv;
}

__global__ void a3v_kernel(){
    __shared__ float As[32][129], Bs[32][65];
    int ksp=blockIdx.x, bm=blockIdx.y*128, bh=blockIdx.z;
    int t=threadIdx.x, tx=t&15, ty=t>>4;
    float acc[8][4]={};
    const float* Ap=g_sim3+(size_t)(bh*ML)*NTOK;
    const float* Vp=g_v+(size_t)bh*NTOK*DH;
    int kbeg=ksp*1024;
    for(int k0=kbeg;k0<kbeg+1024;k0+=32){
        loadA_kmajor(As, Ap, NTOK, bm, k0, t);
        loadB_kn64(Bs, Vp, DH, 0, k0, t);
        __syncthreads();
        fma64(As,Bs,acc,tx,ty);
        __syncthreads();
    }
    #pragma unroll
    for(int i=0;i<8;i++)
        #pragma unroll
        for(int j=0;j<4;j++)
            g_a3vp[(size_t)(ksp*BHN+bh)*ML*DH+(bm+ty*8+i)*DH+tx+(j<<4)]=acc[i][j];
}

__global__ void a3v_reduce_kernel(){
    int e=blockIdx.x*256+threadIdx.x;
    float s=0;
    #pragma unroll
    for(int k=0;k<8;k++) s+=g_a3vp[(size_t)k*BHN*ML*DH+e];
    g_a3v[e]=s;
}

__global__ void z2_kernel(){
    __shared__ float As[32][129], Bs[32][65];
    int bm=blockIdx.x*128, bh=blockIdx.y;
    const float* A=g_z0+((size_t)bh<<16);
    const float* Bp=g_a3v+(size_t)bh*ML*DH;
    int t=threadIdx.x, tx=t&15, ty=t>>4;
    float acc[8][4]={};
    for(int k0=0;k0<256;k0+=32){
        loadA_kmajor(As, A, ML, bm, k0, t);
        loadB_kn64(Bs, Bp, DH, 0, k0, t);
        __syncthreads();
        fma64(As,Bs,acc,tx,ty);
        __syncthreads();
    }
    #pragma unroll
    for(int i=0;i<8;i++)
        #pragma unroll
        for(int j=0;j<4;j++)
            g_Z2[(size_t)bh*ML*DH+(bm+ty*8+i)*DH+tx+(j<<4)]=acc[i][j];
}

__global__ void conv_kernel(const float* __restrict__ cw){
    int idx=blockIdx.x*256+threadIdx.x;
    int d=idx&63, n=(idx>>6)&8191, bh=idx>>19;
    int h=bh&7;
    const float* vp=g_v+(size_t)bh*NTOK*DH+d;
    float s=0;
    #pragma unroll
    for(int kk=0;kk<33;kk++){
        int j=n+kk-16;
        if(j>=0 && j<NTOK) s+=cw[h*33+kk]*vp[(size_t)j*DH];
    }
    g_attn[((size_t)((bh>>3)*NTOK+n))*DIMX+h*64+d]=s;
}

__global__ void a1z2_kernel(){
    __shared__ float As[32][129], Bs[32][65];
    int bm=blockIdx.x*128, bh=blockIdx.y;
    const float* A=g_sim3+(size_t)bh*NTOK*ML;
    const float* Bp=g_Z2+(size_t)bh*ML*DH;
    int t=threadIdx.x, tx=t&15, ty=t>>4;
    float acc[8][4]={};
    for(int k0=0;k0<256;k0+=32){
        loadA_kmajor(As, A, ML, bm, k0, t);
        loadB_kn64(Bs, Bp, DH, 0, k0, t);
        __syncthreads();
        fma64(As,Bs,acc,tx,ty);
        __syncthreads();
    }
    int b=bh>>3, h=bh&7;
    #pragma unroll
    for(int i=0;i<8;i++){
        size_t base=((size_t)(b*NTOK+bm+ty*8+i))*DIMX+h*64;
        #pragma unroll
        for(int j=0;j<4;j++)
            g_attn[base+tx+(j<<4)]+=acc[i][j];
    }
}

extern "C" void kernel_launch(void* const* d_in, const int* in_sizes, int n_in,
                              void* d_out, int out_size){
    const float* x    = (const float*)d_in[0];
    const float* ln_w = (const float*)d_in[2];
    const float* ln_b = (const float*)d_in[3];
    const float* wqkv = (const float*)d_in[4];
    const float* wout = (const float*)d_in[5];
    const float* bout = (const float*)d_in[6];
    const float* cw   = (const float*)d_in[7];
    float* out = (float*)d_out;

    float *z0,*z1,*a2p,*xz,*t1,*t2,*qlp,*klp,*qp,*kp,*sim3p;
    __nv_bfloat16 *bhi,*blo,*wqhi,*wqlo,*wohi,*wolo;
    cudaGetSymbolAddress((void**)&z0, g_z0);
    cudaGetSymbolAddress((void**)&z1, g_z1);
    cudaGetSymbolAddress((void**)&a2p, g_a2);
    cudaGetSymbolAddress((void**)&xz, g_xz);
    cudaGetSymbolAddress((void**)&t1, g_t1);
    cudaGetSymbolAddress((void**)&t2, g_t2);
    cudaGetSymbolAddress((void**)&qlp, g_ql);
    cudaGetSymbolAddress((void**)&klp, g_kl);
    cudaGetSymbolAddress((void**)&qp, g_q);
    cudaGetSymbolAddress((void**)&kp, g_k);
    cudaGetSymbolAddress((void**)&sim3p, g_sim3);
    cudaGetSymbolAddress((void**)&bhi, g_bhi);
    cudaGetSymbolAddress((void**)&blo, g_blo);
    cudaGetSymbolAddress((void**)&wqhi, g_wqhi);
    cudaGetSymbolAddress((void**)&wqlo, g_wqlo);
    cudaGetSymbolAddress((void**)&wohi, g_wohi);
    cudaGetSymbolAddress((void**)&wolo, g_wolo);

    wtrans_kernel<<<dim3(48,16), 256>>>(wqkv, wqhi, wqlo, 512, 1536);
    wtrans_kernel<<<dim3(16,16), 256>>>(wout, wohi, wolo, 512, 512);

    ln_kernel<<<BB*NTOK, 256>>>(x, ln_w, ln_b);

    bf_gemm<<<dim3(12,128), 128>>>(bhi, blo, wqhi, wqlo, 0, nullptr, nullptr, nullptr);

    landmark_kernel<<<BHN*ML, 64>>>();

    sim_kernel<<<dim3(2,2,BHN), 256>>>(qlp, klp, a2p,
        (size_t)ML*DH, (size_t)ML*DH, (size_t)ML*ML, ML);
    softmax256_kernel<<<BHN*ML/8, 256>>>(a2p);

    scal_reset_kernel<<<1,1>>>();
    pinv_sums_kernel<<<BHN, 256>>>();
    zinit_kernel<<<4096, 256>>>();

    float* zc=z0; float* za=z1;
    for(int it=0; it<6; it++){
        mm256_kernel<<<dim3(BHN,4,4),128>>>(a2p, zc, xz, 0.f, -1.f);
        mm256_kernel<<<dim3(BHN,4,4),128>>>(xz, xz, t1, 7.f, 1.f);
        mm256_kernel<<<dim3(BHN,4,4),128>>>(xz, t1, t2, 15.f, 1.f);
        mm256_kernel<<<dim3(BHN,4,4),128>>>(zc, t2, za, 13.f, 0.25f);
        float* tmp=zc; zc=za; za=tmp;
    }

    sim_kernel<<<dim3(64,2,BHN), 256>>>(qlp, kp, sim3p,
        (size_t)ML*DH, (size_t)NTOK*DH, (size_t)ML*NTOK, NTOK);
    softmax3_kernel<<<BHN*ML, 256>>>();
    a3v_kernel<<<dim3(8,2,BHN), 256>>>();
    a3v_reduce_kernel<<<1024, 256>>>();
    z2_kernel<<<dim3(2,BHN), 256>>>();
    conv_kernel<<<32768, 256>>>(cw);

    sim_kernel<<<dim3(2,64,BHN), 256>>>(qp, klp, sim3p,
        (size_t)NTOK*DH, (size_t)ML*DH, (size_t)NTOK*ML, ML);
    softmax256_kernel<<<BHN*NTOK/8, 256>>>(sim3p);
    a1z2_kernel<<<dim3(64,BHN), 256>>>();

    a2bf_kernel<<<8192, 256>>>();
    bf_gemm<<<dim3(4,128), 128>>>(bhi, blo, wohi, wolo, 1, x, bout, out);
}

// round 12
// speedup vs baseline: 1.2859x; 1.1229x over previous
#include <cuda_runtime.h>
#include <cuda_bf16.h>
#include <math.h>
#include <stdint.h>

#define BB 2
#define NTOK 8192
#define DIMX 512
#define NH 8
#define DH 64
#define ML 256
#define BHN 16

__device__ float g_q [BHN*NTOK*DH];
__device__ float g_k [BHN*NTOK*DH];
__device__ float g_v [BHN*NTOK*DH];
__device__ float g_ql[BHN*ML*DH];
__device__ float g_kl[BHN*ML*DH];
__device__ float g_a2[BHN*ML*ML];
__device__ float g_z0[BHN*ML*ML];
__device__ float g_z1[BHN*ML*ML];
__device__ float g_xz[BHN*ML*ML];
__device__ float g_t1[BHN*ML*ML];
__device__ float g_t2[BHN*ML*ML];
__device__ float g_sim3[(size_t)BHN*ML*NTOK];
__device__ float g_a3vp[8*BHN*ML*DH];
__device__ float g_a3v [BHN*ML*DH];
__device__ float g_Z2  [BHN*ML*DH];
__device__ float g_attn[BB*NTOK*DIMX];
__device__ float g_scal[2];
__device__ __nv_bfloat16 g_bhi[BB*NTOK*DIMX];
__device__ __nv_bfloat16 g_blo[BB*NTOK*DIMX];
__device__ __nv_bfloat16 g_wqhi[1536*512];
__device__ __nv_bfloat16 g_wqlo[1536*512];
__device__ __nv_bfloat16 g_wohi[512*512];
__device__ __nv_bfloat16 g_wolo[512*512];

// ================= bf16 mma.sync + ldmatrix =================
__device__ __forceinline__ void mma16816(float* c, const uint32_t* a, const uint32_t* b){
    asm volatile("mma.sync.aligned.m16n8k16.row.col.f32.bf16.bf16.f32 "
        "{%0,%1,%2,%3},{%4,%5,%6,%7},{%8,%9},{%0,%1,%2,%3};"
        : "+f"(c[0]),"+f"(c[1]),"+f"(c[2]),"+f"(c[3])
        : "r"(a[0]),"r"(a[1]),"r"(a[2]),"r"(a[3]),"r"(b[0]),"r"(b[1]));
}
__device__ __forceinline__ uint32_t cvta_s(const void* p){
    uint32_t a;
    asm("{ .reg .u64 t; cvta.to.shared.u64 t, %1; cvt.u32.u64 %0, t; }" : "=r"(a) : "l"(p));
    return a;
}
#define LDSM4(r, a) \
    asm volatile("ldmatrix.sync.aligned.m8n8.x4.shared.b16 {%0,%1,%2,%3}, [%4];" \
        : "=r"((r)[0]),"=r"((r)[1]),"=r"((r)[2]),"=r"((r)[3]) : "r"(a))

#define SWZ(o) ((o) ^ (((o)>>3)&0x70))

// bf16-split GEMM: C[128x128] = A @ B^T over Keff = 3*512.
// SW128 bf16 smem tiles (128B rows), ldmatrix.x4 fragment loads.
// 4 warps, 64x64 warp tile. mode 0: qkv scatter; mode 1: out = x + bias + C.
__global__ void __launch_bounds__(128) bf_gemm(
    const __nv_bfloat16* __restrict__ Ahi, const __nv_bfloat16* __restrict__ Alo,
    const __nv_bfloat16* __restrict__ BhiT, const __nv_bfloat16* __restrict__ BloT,
    int mode, const float* __restrict__ xres, const float* __restrict__ bias,
    float* __restrict__ outp)
{
    __shared__ __align__(1024) unsigned char sA[16384];
    __shared__ __align__(1024) unsigned char sB[16384];
    int t=threadIdx.x, lane=t&31, wid=t>>5;
    int g=lane>>2, tig=lane&3;
    int wm=wid&1, wn=wid>>1;
    int bn=blockIdx.x*128, bm=blockIdx.y*128;
    uint32_t sA32=cvta_s(sA), sB32=cvta_s(sB);
    // per-lane ldmatrix base offsets (row = lane&15, khalf = lane>>4)
    int lrow=lane&15, lkh=(lane>>4)<<4;   // lkh in bytes (0 or 16)

    float acc[4][8][4];
    #pragma unroll
    for(int a=0;a<4;a++)
        #pragma unroll
        for(int b=0;b<8;b++)
            #pragma unroll
            for(int c=0;c<4;c++) acc[a][b][c]=0.f;

    for(int blk=0;blk<24;blk++){
        int seg=blk>>3, kb=(blk&7)<<6;   // 64 bf16 per stage
        const __nv_bfloat16* Asrc=(seg<2)?Ahi:Alo;
        const __nv_bfloat16* Bsrc=(seg==1)?BloT:BhiT;
        #pragma unroll
        for(int i=0;i<8;i++){
            int j=t+(i<<7); int row=j>>3, cg=j&7;
            uint4 v=*(const uint4*)(Asrc+(size_t)(bm+row)*512+kb+(cg<<3));
            *(uint4*)(sA+SWZ(row*128+(cg<<4)))=v;
        }
        #pragma unroll
        for(int i=0;i<8;i++){
            int j=t+(i<<7); int row=j>>3, cg=j&7;
            uint4 v=*(const uint4*)(Bsrc+(size_t)(bn+row)*512+kb+(cg<<3));
            *(uint4*)(sB+SWZ(row*128+(cg<<4)))=v;
        }
        __syncthreads();
        #pragma unroll
        for(int kc=0;kc<4;kc++){
            int kboff=kc*32+lkh;
            uint32_t af[4][4], bfr[8][2];
            #pragma unroll
            for(int mt=0;mt<4;mt++){
                uint32_t addr=sA32+SWZ((wm*64+mt*16+lrow)*128+kboff);
                LDSM4(af[mt], addr);
            }
            #pragma unroll
            for(int p=0;p<4;p++){
                uint32_t r4[4];
                uint32_t addr=sB32+SWZ((wn*64+p*16+lrow)*128+kboff);
                LDSM4(r4, addr);
                bfr[2*p][0]=r4[0]; bfr[2*p+1][0]=r4[1];
                bfr[2*p][1]=r4[2]; bfr[2*p+1][1]=r4[3];
            }
            #pragma unroll
            for(int mt=0;mt<4;mt++)
                #pragma unroll
                for(int nt=0;nt<8;nt++)
                    mma16816(acc[mt][nt], af[mt], bfr[nt]);
        }
        __syncthreads();
    }

    #pragma unroll
    for(int mt=0;mt<4;mt++)
        #pragma unroll
        for(int nt=0;nt<8;nt++)
            #pragma unroll
            for(int ci=0;ci<4;ci++){
                int row=bm+wm*64+mt*16+g+((ci>>1)<<3);
                int col=bn+wn*64+nt*8+(tig<<1)+(ci&1);
                float val=acc[mt][nt][ci];
                if(mode==0){
                    int b_=row>>13, n=row&8191;
                    int s=col>>9, inner=col&511, h=inner>>6, d=inner&63;
                    size_t o=((size_t)((b_*NH+h)*NTOK+n))*DH+d;
                    if(s==0) g_q[o]=val*0.125f;
                    else if(s==1) g_k[o]=val;
                    else g_v[o]=val;
                } else {
                    size_t o=(size_t)row*DIMX+col;
                    outp[o]=xres[o]+bias[col]+val;
                }
            }
}

// ---- weight transpose + bf16 hi/lo split ----
__global__ void wtrans_kernel(const float* __restrict__ W,
                              __nv_bfloat16* __restrict__ BhiT, __nv_bfloat16* __restrict__ BloT,
                              int K, int N){
    __shared__ float tile[32][33];
    int k0=blockIdx.y*32, n0=blockIdx.x*32;
    int tx=threadIdx.x&31, ty=threadIdx.x>>5;
    #pragma unroll
    for(int i=0;i<32;i+=8) tile[ty+i][tx]=W[(size_t)(k0+ty+i)*N+n0+tx];
    __syncthreads();
    #pragma unroll
    for(int i=0;i<32;i+=8){
        int n=n0+ty+i, k=k0+tx;
        float v=tile[tx][ty+i];
        __nv_bfloat16 h=__float2bfloat16(v);
        BhiT[(size_t)n*K+k]=h;
        BloT[(size_t)n*K+k]=__float2bfloat16(v-__bfloat162float(h));
    }
}

__global__ void a2bf_kernel(){
    size_t i4=((size_t)blockIdx.x*256+threadIdx.x)*4;
    float4 v=*(const float4*)(g_attn+i4);
    float xs[4]={v.x,v.y,v.z,v.w};
    #pragma unroll
    for(int j=0;j<4;j++){
        __nv_bfloat16 h=__float2bfloat16(xs[j]);
        g_bhi[i4+j]=h;
        g_blo[i4+j]=__float2bfloat16(xs[j]-__bfloat162float(h));
    }
}

__global__ void ln_kernel(const float* __restrict__ x, const float* __restrict__ w,
                          const float* __restrict__ bp){
    int row=blockIdx.x, t=threadIdx.x;
    const float* xr=x+(size_t)row*DIMX;
    float v0=xr[t], v1=xr[t+256];
    float s=v0+v1, sq=v0*v0+v1*v1;
    __shared__ float r1[8], r2[8];
    #pragma unroll
    for(int o=16;o;o>>=1){ s+=__shfl_xor_sync(~0u,s,o); sq+=__shfl_xor_sync(~0u,sq,o); }
    if((t&31)==0){ r1[t>>5]=s; r2[t>>5]=sq; }
    __syncthreads();
    float ss=0, qq=0;
    #pragma unroll
    for(int i=0;i<8;i++){ ss+=r1[i]; qq+=r2[i]; }
    float mean=ss*(1.f/512.f);
    float rstd=rsqrtf(qq*(1.f/512.f)-mean*mean+1e-5f);
    float y0=(v0-mean)*rstd*w[t]+bp[t];
    float y1=(v1-mean)*rstd*w[t+256]+bp[t+256];
    __nv_bfloat16 h0=__float2bfloat16(y0), h1=__float2bfloat16(y1);
    size_t b=(size_t)row*DIMX;
    g_bhi[b+t]=h0;      g_blo[b+t]=__float2bfloat16(y0-__bfloat162float(h0));
    g_bhi[b+t+256]=h1;  g_blo[b+t+256]=__float2bfloat16(y1-__bfloat162float(h1));
}

// ================= fp32 SIMT cores =================
__device__ __forceinline__ void loadA_kmajor(float (*As)[129], const float* __restrict__ Ag,
                                             int lda, int bm, int k0, int t){
    #pragma unroll
    for(int i=0;i<4;i++){
        int q=t+(i<<8); int r=q>>3; int kq=q&7;
        float4 v=*(const float4*)(Ag+(size_t)(bm+r)*lda+k0+(kq<<2));
        As[(kq<<2)+0][r]=v.x; As[(kq<<2)+1][r]=v.y;
        As[(kq<<2)+2][r]=v.z; As[(kq<<2)+3][r]=v.w;
    }
}
__device__ __forceinline__ void loadB_kn64(float (*Bs)[65], const float* __restrict__ Bg,
                                           int ldb, int bn, int k0, int t){
    #pragma unroll
    for(int i=0;i<2;i++){
        int q=t+(i<<8); int kk=q>>4; int cq=q&15;
        float4 v=*(const float4*)(Bg+(size_t)(k0+kk)*ldb+bn+(cq<<2));
        Bs[kk][(cq<<2)+0]=v.x; Bs[kk][(cq<<2)+1]=v.y;
        Bs[kk][(cq<<2)+2]=v.z; Bs[kk][(cq<<2)+3]=v.w;
    }
}
__device__ __forceinline__ void fma128(const float (*As)[129], const float (*Bs)[129],
                                       float acc[8][8], int tx, int ty){
    #pragma unroll
    for(int kk=0;kk<32;kk++){
        float a[8], b[8];
        #pragma unroll
        for(int i=0;i<8;i++) a[i]=As[kk][ty*8+i];
        #pragma unroll
        for(int j=0;j<8;j++) b[j]=Bs[kk][tx+(j<<4)];
        #pragma unroll
        for(int i=0;i<8;i++)
            #pragma unroll
            for(int j=0;j<8;j++) acc[i][j]+=a[i]*b[j];
    }
}
__device__ __forceinline__ void fma64(const float (*As)[129], const float (*Bs)[65],
                                      float acc[8][4], int tx, int ty){
    #pragma unroll
    for(int kk=0;kk<32;kk++){
        float a[8], b[4];
        #pragma unroll
        for(int i=0;i<8;i++) a[i]=As[kk][ty*8+i];
        #pragma unroll
        for(int j=0;j<4;j++) b[j]=Bs[kk][tx+(j<<4)];
        #pragma unroll
        for(int i=0;i<8;i++)
            #pragma unroll
            for(int j=0;j<4;j++) acc[i][j]+=a[i]*b[j];
    }
}

__global__ void landmark_kernel(){
    int blk=blockIdx.x, bh=blk>>8, m=blk&255, d=threadIdx.x;
    const float* qp=g_q+((size_t)(bh*NTOK+m*32))*DH+d;
    const float* kp=g_k+((size_t)(bh*NTOK+m*32))*DH+d;
    float sq=0,sk=0;
    #pragma unroll
    for(int j=0;j<32;j++){ sq+=qp[(size_t)j*DH]; sk+=kp[(size_t)j*DH]; }
    g_ql[(bh*ML+m)*DH+d]=sq*(1.f/32.f);
    g_kl[(bh*ML+m)*DH+d]=sk*(1.f/32.f);
}

__global__ void sim_kernel(const float* __restrict__ Abase, const float* __restrict__ Bbase,
                           float* __restrict__ Cbase, size_t aBH, size_t bBH, size_t cBH, int ldC){
    __shared__ float As[32][129], Bs[32][129];
    int t=threadIdx.x, tx=t&15, ty=t>>4;
    int bh=blockIdx.z;
    int bn=blockIdx.x*128, bm=blockIdx.y*128;
    const float* A=Abase+(size_t)bh*aBH;
    const float* B=Bbase+(size_t)bh*bBH;
    float* C=Cbase+(size_t)bh*cBH;
    float acc[8][8]={};
    for(int k0=0;k0<64;k0+=32){
        loadA_kmajor(As, A, DH, bm, k0, t);
        loadA_kmajor(Bs, B, DH, bn, k0, t);
        __syncthreads();
        fma128(As,Bs,acc,tx,ty);
        __syncthreads();
    }
    #pragma unroll
    for(int i=0;i<8;i++)
        #pragma unroll
        for(int j=0;j<8;j++)
            C[(size_t)(bm+ty*8+i)*ldC+bn+tx+(j<<4)]=acc[i][j];
}

__global__ void softmax256_kernel(float* __restrict__ base){
    int w=threadIdx.x>>5, lane=threadIdx.x&31;
    size_t row=(size_t)blockIdx.x*8+w;
    float* p=base+row*ML;
    float4 v0=*(float4*)(p+lane*8);
    float4 v1=*(float4*)(p+lane*8+4);
    float mx=fmaxf(fmaxf(fmaxf(v0.x,v0.y),fmaxf(v0.z,v0.w)),
                   fmaxf(fmaxf(v1.x,v1.y),fmaxf(v1.z,v1.w)));
    #pragma unroll
    for(int o=16;o;o>>=1) mx=fmaxf(mx,__shfl_xor_sync(~0u,mx,o));
    v0.x=__expf(v0.x-mx); v0.y=__expf(v0.y-mx); v0.z=__expf(v0.z-mx); v0.w=__expf(v0.w-mx);
    v1.x=__expf(v1.x-mx); v1.y=__expf(v1.y-mx); v1.z=__expf(v1.z-mx); v1.w=__expf(v1.w-mx);
    float s=v0.x+v0.y+v0.z+v0.w+v1.x+v1.y+v1.z+v1.w;
    #pragma unroll
    for(int o=16;o;o>>=1) s+=__shfl_xor_sync(~0u,s,o);
    float inv=1.f/s;
    v0.x*=inv; v0.y*=inv; v0.z*=inv; v0.w*=inv;
    v1.x*=inv; v1.y*=inv; v1.z*=inv; v1.w*=inv;
    *(float4*)(p+lane*8)=v0;
    *(float4*)(p+lane*8+4)=v1;
}

__global__ void scal_reset_kernel(){ g_scal[0]=0.f; g_scal[1]=0.f; }

__global__ void pinv_sums_kernel(){
    int bh=blockIdx.x, t=threadIdx.x;
    const float* A=g_a2+((size_t)bh<<16);
    float rs=0, cs=0;
    const float4* Ar=(const float4*)(A+(size_t)t*ML);
    #pragma unroll
    for(int j=0;j<64;j++){ float4 v=Ar[j]; rs+=fabsf(v.x)+fabsf(v.y)+fabsf(v.z)+fabsf(v.w); }
    for(int j=0;j<ML;j++) cs+=fabsf(A[(size_t)j*ML+t]);
    #pragma unroll
    for(int o=16;o;o>>=1){ rs=fmaxf(rs,__shfl_xor_sync(~0u,rs,o)); cs=fmaxf(cs,__shfl_xor_sync(~0u,cs,o)); }
    __shared__ float r1[8], r2[8];
    if((t&31)==0){ r1[t>>5]=rs; r2[t>>5]=cs; }
    __syncthreads();
    if(t==0){
        float m1=r1[0], m2=r2[0];
        #pragma unroll
        for(int k=1;k<8;k++){ m1=fmaxf(m1,r1[k]); m2=fmaxf(m2,r2[k]); }
        atomicMax((int*)&g_scal[0], __float_as_int(m1));
        atomicMax((int*)&g_scal[1], __float_as_int(m2));
    }
}

__global__ void zinit_kernel(){
    int e=blockIdx.x*256+threadIdx.x;
    float inv=1.f/(g_scal[0]*g_scal[1]);
    int bh=e>>16, r=(e>>8)&255, c=e&255;
    g_z0[e]=g_a2[(bh<<16)+(c<<8)+r]*inv;
}

// ---- batched 256^3: C = alpha * A @ (cdiag*I - B) ----
__global__ void __launch_bounds__(128) mm256_kernel(
        const float* __restrict__ Ag, const float* __restrict__ Bg,
        float* __restrict__ Cg, float cdiag, float alpha){
    int bh=blockIdx.x;
    const float* A=Ag+((size_t)bh<<16);
    const float* B=Bg+((size_t)bh<<16);
    float* C=Cg+((size_t)bh<<16);
    int bm=blockIdx.y*64, bn=blockIdx.z*64;
    __shared__ float As[32][65], Bs[32][65];
    int t=threadIdx.x, tx=t&15, ty=t>>4;
    float acc[8][4]={};
    for(int k0=0;k0<256;k0+=32){
        #pragma unroll
        for(int i=0;i<4;i++){
            int j=t+(i<<7); int r=j>>3, kq=j&7;
            float4 v=*(const float4*)(A+(size_t)(bm+r)*256+k0+(kq<<2));
            As[(kq<<2)+0][r]=v.x; As[(kq<<2)+1][r]=v.y;
            As[(kq<<2)+2][r]=v.z; As[(kq<<2)+3][r]=v.w;
        }
        #pragma unroll
        for(int i=0;i<16;i++){
            int j=t+(i<<7); int kk=j>>6, c=j&63;
            int gk=k0+kk, gc=bn+c;
            float bv=B[(size_t)gk*256+gc];
            Bs[kk][c]=(gk==gc)?(cdiag-bv):(-bv);
        }
        __syncthreads();
        #pragma unroll
        for(int kk=0;kk<32;kk++){
            float a[8], b[4];
            #pragma unroll
            for(int i=0;i<8;i++) a[i]=As[kk][ty*8+i];
            #pragma unroll
            for(int j=0;j<4;j++) b[j]=Bs[kk][tx+(j<<4)];
            #pragma unroll
            for(int i=0;i<8;i++)
                #pragma unroll
                for(int j=0;j<4;j++) acc[i][j]+=a[i]*b[j];
        }
        __syncthreads();
    }
    #pragma unroll
    for(int i=0;i<8;i++)
        #pragma unroll
        for(int j=0;j<4;j++)
            C[(size_t)(bm+ty*8+i)*256+bn+tx+(j<<4)]=alpha*acc[i][j];
}

__global__ void softmax3_kernel(){
    int row=blockIdx.x, t=threadIdx.x;
    float* p=g_sim3+(size_t)row*NTOK;
    float v[32], mx=-3.0e38f;
    #pragma unroll
    for(int i=0;i<32;i++){ v[i]=p[t+(i<<8)]; mx=fmaxf(mx,v[i]); }
    __shared__ float red[8];
    #pragma unroll
    for(int o=16;o;o>>=1) mx=fmaxf(mx,__shfl_xor_sync(~0u,mx,o));
    if((t&31)==0) red[t>>5]=mx;
    __syncthreads();
    mx=red[0];
    #pragma unroll
    for(int k=1;k<8;k++) mx=fmaxf(mx,red[k]);
    float s=0;
    #pragma unroll
    for(int i=0;i<32;i++){ v[i]=__expf(v[i]-mx); s+=v[i]; }
    #pragma unroll
    for(int o=16;o;o>>=1) s+=__shfl_xor_sync(~0u,s,o);
    __syncthreads();
    if((t&31)==0) red[t>>5]=s;
    __syncthreads();
    s=0;
    #pragma unroll
    for(int k=0;k<8;k++) s+=red[k];
    float inv=1.f/s;
    #pragma unroll
    for(int i=0;i<32;i++) p[t+(i<<8)]=v[i]*inv;
}

__global__ void a3v_kernel(){
    __shared__ float As[32][129], Bs[32][65];
    int ksp=blockIdx.x, bm=blockIdx.y*128, bh=blockIdx.z;
    int t=threadIdx.x, tx=t&15, ty=t>>4;
    float acc[8][4]={};
    const float* Ap=g_sim3+(size_t)(bh*ML)*NTOK;
    const float* Vp=g_v+(size_t)bh*NTOK*DH;
    int kbeg=ksp*1024;
    for(int k0=kbeg;k0<kbeg+1024;k0+=32){
        loadA_kmajor(As, Ap, NTOK, bm, k0, t);
        loadB_kn64(Bs, Vp, DH, 0, k0, t);
        __syncthreads();
        fma64(As,Bs,acc,tx,ty);
        __syncthreads();
    }
    #pragma unroll
    for(int i=0;i<8;i++)
        #pragma unroll
        for(int j=0;j<4;j++)
            g_a3vp[(size_t)(ksp*BHN+bh)*ML*DH+(bm+ty*8+i)*DH+tx+(j<<4)]=acc[i][j];
}

__global__ void a3v_reduce_kernel(){
    int e=blockIdx.x*256+threadIdx.x;
    float s=0;
    #pragma unroll
    for(int k=0;k<8;k++) s+=g_a3vp[(size_t)k*BHN*ML*DH+e];
    g_a3v[e]=s;
}

__global__ void z2_kernel(){
    __shared__ float As[32][129], Bs[32][65];
    int bm=blockIdx.x*128, bh=blockIdx.y;
    const float* A=g_z0+((size_t)bh<<16);
    const float* Bp=g_a3v+(size_t)bh*ML*DH;
    int t=threadIdx.x, tx=t&15, ty=t>>4;
    float acc[8][4]={};
    for(int k0=0;k0<256;k0+=32){
        loadA_kmajor(As, A, ML, bm, k0, t);
        loadB_kn64(Bs, Bp, DH, 0, k0, t);
        __syncthreads();
        fma64(As,Bs,acc,tx,ty);
        __syncthreads();
    }
    #pragma unroll
    for(int i=0;i<8;i++)
        #pragma unroll
        for(int j=0;j<4;j++)
            g_Z2[(size_t)bh*ML*DH+(bm+ty*8+i)*DH+tx+(j<<4)]=acc[i][j];
}

__global__ void conv_kernel(const float* __restrict__ cw){
    int idx=blockIdx.x*256+threadIdx.x;
    int d=idx&63, n=(idx>>6)&8191, bh=idx>>19;
    int h=bh&7;
    const float* vp=g_v+(size_t)bh*NTOK*DH+d;
    float s=0;
    #pragma unroll
    for(int kk=0;kk<33;kk++){
        int j=n+kk-16;
        if(j>=0 && j<NTOK) s+=cw[h*33+kk]*vp[(size_t)j*DH];
    }
    g_attn[((size_t)((bh>>3)*NTOK+n))*DIMX+h*64+d]=s;
}

__global__ void a1z2_kernel(){
    __shared__ float As[32][129], Bs[32][65];
    int bm=blockIdx.x*128, bh=blockIdx.y;
    const float* A=g_sim3+(size_t)bh*NTOK*ML;
    const float* Bp=g_Z2+(size_t)bh*ML*DH;
    int t=threadIdx.x, tx=t&15, ty=t>>4;
    float acc[8][4]={};
    for(int k0=0;k0<256;k0+=32){
        loadA_kmajor(As, A, ML, bm, k0, t);
        loadB_kn64(Bs, Bp, DH, 0, k0, t);
        __syncthreads();
        fma64(As,Bs,acc,tx,ty);
        __syncthreads();
    }
    int b=bh>>3, h=bh&7;
    #pragma unroll
    for(int i=0;i<8;i++){
        size_t base=((size_t)(b*NTOK+bm+ty*8+i))*DIMX+h*64;
        #pragma unroll
        for(int j=0;j<4;j++)
            g_attn[base+tx+(j<<4)]+=acc[i][j];
    }
}

extern "C" void kernel_launch(void* const* d_in, const int* in_sizes, int n_in,
                              void* d_out, int out_size){
    const float* x    = (const float*)d_in[0];
    const float* ln_w = (const float*)d_in[2];
    const float* ln_b = (const float*)d_in[3];
    const float* wqkv = (const float*)d_in[4];
    const float* wout = (const float*)d_in[5];
    const float* bout = (const float*)d_in[6];
    const float* cw   = (const float*)d_in[7];
    float* out = (float*)d_out;

    float *z0,*z1,*a2p,*xz,*t1,*t2,*qlp,*klp,*qp,*kp,*sim3p;
    __nv_bfloat16 *bhi,*blo,*wqhi,*wqlo,*wohi,*wolo;
    cudaGetSymbolAddress((void**)&z0, g_z0);
    cudaGetSymbolAddress((void**)&z1, g_z1);
    cudaGetSymbolAddress((void**)&a2p, g_a2);
    cudaGetSymbolAddress((void**)&xz, g_xz);
    cudaGetSymbolAddress((void**)&t1, g_t1);
    cudaGetSymbolAddress((void**)&t2, g_t2);
    cudaGetSymbolAddress((void**)&qlp, g_ql);
    cudaGetSymbolAddress((void**)&klp, g_kl);
    cudaGetSymbolAddress((void**)&qp, g_q);
    cudaGetSymbolAddress((void**)&kp, g_k);
    cudaGetSymbolAddress((void**)&sim3p, g_sim3);
    cudaGetSymbolAddress((void**)&bhi, g_bhi);
    cudaGetSymbolAddress((void**)&blo, g_blo);
    cudaGetSymbolAddress((void**)&wqhi, g_wqhi);
    cudaGetSymbolAddress((void**)&wqlo, g_wqlo);
    cudaGetSymbolAddress((void**)&wohi, g_wohi);
    cudaGetSymbolAddress((void**)&wolo, g_wolo);

    wtrans_kernel<<<dim3(48,16), 256>>>(wqkv, wqhi, wqlo, 512, 1536);
    wtrans_kernel<<<dim3(16,16), 256>>>(wout, wohi, wolo, 512, 512);

    ln_kernel<<<BB*NTOK, 256>>>(x, ln_w, ln_b);

    bf_gemm<<<dim3(12,128), 128>>>(bhi, blo, wqhi, wqlo, 0, nullptr, nullptr, nullptr);

    landmark_kernel<<<BHN*ML, 64>>>();

    sim_kernel<<<dim3(2,2,BHN), 256>>>(qlp, klp, a2p,
        (size_t)ML*DH, (size_t)ML*DH, (size_t)ML*ML, ML);
    softmax256_kernel<<<BHN*ML/8, 256>>>(a2p);

    scal_reset_kernel<<<1,1>>>();
    pinv_sums_kernel<<<BHN, 256>>>();
    zinit_kernel<<<4096, 256>>>();

    float* zc=z0; float* za=z1;
    for(int it=0; it<6; it++){
        mm256_kernel<<<dim3(BHN,4,4),128>>>(a2p, zc, xz, 0.f, -1.f);
        mm256_kernel<<<dim3(BHN,4,4),128>>>(xz, xz, t1, 7.f, 1.f);
        mm256_kernel<<<dim3(BHN,4,4),128>>>(xz, t1, t2, 15.f, 1.f);
        mm256_kernel<<<dim3(BHN,4,4),128>>>(zc, t2, za, 13.f, 0.25f);
        float* tmp=zc; zc=za; za=tmp;
    }

    sim_kernel<<<dim3(64,2,BHN), 256>>>(qlp, kp, sim3p,
        (size_t)ML*DH, (size_t)NTOK*DH, (size_t)ML*NTOK, NTOK);
    softmax3_kernel<<<BHN*ML, 256>>>();
    a3v_kernel<<<dim3(8,2,BHN), 256>>>();
    a3v_reduce_kernel<<<1024, 256>>>();
    z2_kernel<<<dim3(2,BHN), 256>>>();
    conv_kernel<<<32768, 256>>>(cw);

    sim_kernel<<<dim3(2,64,BHN), 256>>>(qp, klp, sim3p,
        (size_t)NTOK*DH, (size_t)ML*DH, (size_t)NTOK*ML, ML);
    softmax256_kernel<<<BHN*NTOK/8, 256>>>(sim3p);
    a1z2_kernel<<<dim3(64,BHN), 256>>>();

    a2bf_kernel<<<8192, 256>>>();
    bf_gemm<<<dim3(4,128), 128>>>(bhi, blo, wohi, wolo, 1, x, bout, out);
}